// round 8
// baseline (speedup 1.0000x reference)
#include <cuda_runtime.h>
#include <cuda_fp16.h>
#include <cstdint>

#define DEV_INLINE __device__ __forceinline__

// ---------------- problem constants ----------------
constexpr int NN   = 100000;
constexpr int NE   = 300000;
constexpr int D    = 256;
constexpr int HID2 = 512;
constexpr int NHID = 512;
constexpr int NOUT = 768;
constexpr int NG   = 4096;
constexpr int LGIN = 4;

// ---------------- scratch (device globals) ----------------
__device__ float  g_agg [(size_t)NN * D];
__device__ float  g_h   [(size_t)NN * D];
__device__ __half g_th  [(size_t)NN * HID2];   // GIN hidden, fp16
__device__ float  g_pool[(size_t)NG * D];
__device__ float  g_cnt [NG];
__device__ float  g_p1  [(size_t)NG * NHID];
__device__ float  g_bns [5 * D];
__device__ float  g_bnb [5 * D];
__device__ int    g_is64;
// fragment-order fp16 weights (uint4 = 8 halves, mma.m16n8k16 B-frag pairs)
__device__ uint4  g_wf1 [(size_t)LGIN * D * HID2 / 8];
__device__ uint4  g_wf2 [(size_t)LGIN * HID2 * D / 8];
__device__ uint4  g_wfp1[(size_t)D * NHID / 8];
__device__ uint4  g_wfp2[(size_t)NHID * NOUT / 8];

// ---------------- PTX helpers ----------------
DEV_INLINE void red_add_v4(float* p, float4 v) {
    asm volatile("red.global.add.v4.f32 [%0], {%1, %2, %3, %4};"
                 :: "l"(p), "f"(v.x), "f"(v.y), "f"(v.z), "f"(v.w) : "memory");
}
DEV_INLINE long long load_index(const void* base, long long i, int is64) {
    if (is64) return ((const long long*)base)[i];
    return (long long)((const int*)base)[i];
}
DEV_INLINE uint32_t smem_u32(const void* p) {
    uint32_t a;
    asm("{ .reg .u64 t; cvta.to.shared.u64 t, %1; cvt.u32.u64 %0, t; }" : "=r"(a) : "l"(p));
    return a;
}
DEV_INLINE void cp_async16s(uint32_t saddr, const void* g) {
    asm volatile("cp.async.cg.shared.global [%0], [%1], 16;" :: "r"(saddr), "l"(g) : "memory");
}
DEV_INLINE void cp_commit() { asm volatile("cp.async.commit_group;" ::: "memory"); }
template<int Nq> DEV_INLINE void cp_wait() { asm volatile("cp.async.wait_group %0;" :: "n"(Nq) : "memory"); }

DEV_INLINE uint32_t pack_h2(float a, float b) {
    __half2 h = __floats2half2_rn(a, b);
    return *(uint32_t*)&h;
}
DEV_INLINE void mma_f16(float4& c, uint32_t a0, uint32_t a1, uint32_t a2, uint32_t a3,
                        uint32_t b0, uint32_t b1) {
    asm volatile(
        "mma.sync.aligned.m16n8k16.row.col.f32.f16.f16.f32 "
        "{%0,%1,%2,%3}, {%4,%5,%6,%7}, {%8,%9}, {%0,%1,%2,%3};"
        : "+f"(c.x), "+f"(c.y), "+f"(c.z), "+f"(c.w)
        : "r"(a0), "r"(a1), "r"(a2), "r"(a3), "r"(b0), "r"(b1));
}

// ---------------- small kernels ----------------
__global__ void detect_idx(const unsigned int* __restrict__ w) {
    unsigned int nz = 0;
    #pragma unroll 1
    for (int k = 0; k < 256; k++) nz |= w[2 * k + 1];
    g_is64 = (nz == 0u) ? 1 : 0;
}

__global__ void bn_precompute(const float* __restrict__ gamma, const float* __restrict__ beta,
                              const float* __restrict__ mean,  const float* __restrict__ var) {
    int i = blockIdx.x * blockDim.x + threadIdx.x;
    if (i < 5 * D) {
        float s = gamma[i] * rsqrtf(var[i] + 1e-5f);
        g_bns[i] = s;
        g_bnb[i] = beta[i] - mean[i] * s;
    }
}

// Pack weight w[K][N] (row-major fp32) into fp16 m16n8k16 fragment order.
__global__ void prep_wh(const float* __restrict__ src, uint4* __restrict__ dst, int K, int N) {
    int id = blockIdx.x * blockDim.x + threadIdx.x;
    int K16 = K >> 4;
    int total = (N >> 8) * K16 * 512;
    if (id >= total) return;
    int lane = id & 31;
    int p    = (id >> 5) & 15;
    int blk  = id >> 9;
    int kt   = blk % K16;
    int nb   = blk / K16;
    int g = lane >> 2, tig = lane & 3;
    int c0 = nb * 256 + p * 16 + g;
    int c1 = c0 + 8;
    int k0 = kt * 16 + tig * 2;
    uint32_t u0 = pack_h2(src[(size_t)k0 * N + c0],       src[(size_t)(k0 + 1) * N + c0]);
    uint32_t u1 = pack_h2(src[(size_t)(k0 + 8) * N + c0], src[(size_t)(k0 + 9) * N + c0]);
    uint32_t u2 = pack_h2(src[(size_t)k0 * N + c1],       src[(size_t)(k0 + 1) * N + c1]);
    uint32_t u3 = pack_h2(src[(size_t)(k0 + 8) * N + c1], src[(size_t)(k0 + 9) * N + c1]);
    dst[id] = make_uint4(u0, u1, u2, u3);
}

__global__ void init_agg(float* __restrict__ agg, const float* __restrict__ hin,
                         const float* __restrict__ eps_arr, int l) {
    size_t i = (size_t)blockIdx.x * blockDim.x + threadIdx.x;
    if (i < (size_t)NN * D / 4) {
        float s = 1.0f + __ldg(&eps_arr[l]);
        float4 v = ((const float4*)hin)[i];
        v.x *= s; v.y *= s; v.z *= s; v.w *= s;
        ((float4*)agg)[i] = v;
    }
}

__global__ void scatter_edges(float* __restrict__ agg, const float* __restrict__ h,
                              const void* __restrict__ ei) {
    int wid = (int)(((size_t)blockIdx.x * blockDim.x + threadIdx.x) >> 5);
    if (wid >= NE) return;
    int lane = threadIdx.x & 31;
    int is64 = g_is64;
    long long s = load_index(ei, wid, is64);
    long long d = load_index(ei, (long long)NE + wid, is64);
    const float4* hs = (const float4*)(h + (size_t)s * D);
    float*        ad = agg + (size_t)d * D;
    float4 v0 = __ldg(hs + lane);
    float4 v1 = __ldg(hs + 32 + lane);
    red_add_v4(ad + lane * 4,       v0);
    red_add_v4(ad + 128 + lane * 4, v1);
}

__global__ void pool_scatter(float* __restrict__ pool, float* __restrict__ cnt,
                             const float* __restrict__ h, const void* __restrict__ batch) {
    int wid = (int)(((size_t)blockIdx.x * blockDim.x + threadIdx.x) >> 5);
    if (wid >= NN) return;
    int lane = threadIdx.x & 31;
    long long g = load_index(batch, wid, g_is64);
    const float4* hs = (const float4*)(h + (size_t)wid * D);
    float*        pd = pool + (size_t)g * D;
    float4 v0 = __ldg(hs + lane);
    float4 v1 = __ldg(hs + 32 + lane);
    red_add_v4(pd + lane * 4,       v0);
    red_add_v4(pd + 128 + lane * 4, v1);
    if (lane == 0) atomicAdd(&cnt[g], 1.0f);
}

__global__ void zero_pool(float* __restrict__ pool, float* __restrict__ cnt) {
    int i = blockIdx.x * blockDim.x + threadIdx.x;
    if (i < NG * D / 4) ((float4*)pool)[i] = make_float4(0.f, 0.f, 0.f, 0.f);
    if (i < NG) cnt[i] = 0.f;
}

__global__ void normalize_pool(float* __restrict__ pool, const float* __restrict__ cnt) {
    int i = blockIdx.x * blockDim.x + threadIdx.x;
    if (i < NG * D / 4) {
        int g = i >> 6;
        float s = 1.0f / fmaxf(__ldg(&cnt[g]), 1.0f);
        float4 v = ((float4*)pool)[i];
        v.x *= s; v.y *= s; v.z *= s; v.w *= s;
        ((float4*)pool)[i] = v;
    }
}

// ---------------- fp16 mma.sync GEMM, 512 threads ----------------
// CTA 128x256, 16 warps as 4(m) x 4(n), warp tile 32x64, m16n8k16, fp32 accum.
// SMEM per stage (u32): A [8 mt][4 reg][32 lane] = 1024, B [16 p][32 lane] uint4 = 2048.
template<int EPI, bool WAGG, bool AH, bool CH>
__global__ __launch_bounds__(512)
void hgemm(const void* __restrict__ Ain, const uint4* __restrict__ Wf,
           const float* __restrict__ bias, void* __restrict__ Cout,
           int M, int K, int Ntotal,
           const float* __restrict__ bns, const float* __restrict__ bnb,
           float* __restrict__ aggout, const float* __restrict__ eps_arr, int eps_idx)
{
    __shared__ uint32_t smu[2][3072];

    const int tid  = threadIdx.x;
    const int w    = tid >> 5, lane = tid & 31;
    const int wm   = w >> 2,   wn   = w & 3;        // 4 x 4 warp grid
    const int row0 = blockIdx.y * 128;
    const int col0 = blockIdx.x * 256;
    const int K16  = K >> 4;

    // A producer mapping (threads < 256): row rr, k-half kk8
    const bool aprod = tid < 256;
    const int rr   = (tid & 255) >> 1;
    const int kk8  = tid & 1;
    const int mt   = rr >> 4;
    const int g    = rr & 7;
    const int reg  = ((rr >> 3) & 1) + 2 * kk8;
    const int soff = mt * 128 + reg * 32 + g * 4;
    int rrg = row0 + rr; if (rrg > M - 1) rrg = M - 1;

    const __half* Ah = (const __half*)Ain;
    const float*  Af = (const float*)Ain;
    const uint4*  Bsrc = Wf + (size_t)blockIdx.x * K16 * 512;

    float4 acc[2][8];
    #pragma unroll
    for (int i = 0; i < 2; i++)
        #pragma unroll
        for (int j = 0; j < 8; j++) acc[i][j] = make_float4(0.f, 0.f, 0.f, 0.f);

    uint4  avh;
    float4 av0, av1;

    // prologue: stage 0
    {
        if (aprod) {
            if (AH) avh = *(const uint4*)(Ah + (size_t)rrg * K + kk8 * 8);
            else { const float4* p = (const float4*)(Af + (size_t)rrg * K + kk8 * 8);
                   av0 = __ldg(p); av1 = __ldg(p + 1); }
        }
        cp_async16s(smem_u32(&smu[0][1024 + tid * 4]), Bsrc + tid);   // 512 uint4 = B stage
        cp_commit();
        if (aprod) {
            uint4 st;
            if (AH) st = avh;
            else st = make_uint4(pack_h2(av0.x, av0.y), pack_h2(av0.z, av0.w),
                                 pack_h2(av1.x, av1.y), pack_h2(av1.z, av1.w));
            *(uint4*)(&smu[0][soff]) = st;
        }
        cp_wait<0>();
        __syncthreads();
    }

    for (int kt = 0; kt < K16; kt++) {
        const int st = kt & 1;
        const bool hn = (kt + 1) < K16;
        if (hn) {
            if (aprod) {
                if (AH) avh = *(const uint4*)(Ah + (size_t)rrg * K + (kt + 1) * 16 + kk8 * 8);
                else { const float4* p = (const float4*)(Af + (size_t)rrg * K + (kt + 1) * 16 + kk8 * 8);
                       av0 = __ldg(p); av1 = __ldg(p + 1); }
            }
            cp_async16s(smem_u32(&smu[st ^ 1][1024 + tid * 4]), Bsrc + (size_t)(kt + 1) * 512 + tid);
            cp_commit();
        }
        // ---- compute stage st ----
        const uint32_t* sA = smu[st];
        const uint32_t* sB = smu[st] + 1024;
        uint4 b[4];
        #pragma unroll
        for (int jp = 0; jp < 4; jp++)
            b[jp] = *(const uint4*)(sB + ((wn * 4 + jp) * 32 + lane) * 4);
        #pragma unroll
        for (int i = 0; i < 2; i++) {
            const uint32_t* ab = sA + (wm * 2 + i) * 128 + lane;
            uint32_t a0 = ab[0], a1 = ab[32], a2 = ab[64], a3 = ab[96];
            #pragma unroll
            for (int jp = 0; jp < 4; jp++) {
                mma_f16(acc[i][jp * 2],     a0, a1, a2, a3, b[jp].x, b[jp].y);
                mma_f16(acc[i][jp * 2 + 1], a0, a1, a2, a3, b[jp].z, b[jp].w);
            }
        }
        if (hn) {
            if (aprod) {
                uint4 stv;
                if (AH) stv = avh;
                else stv = make_uint4(pack_h2(av0.x, av0.y), pack_h2(av0.z, av0.w),
                                      pack_h2(av1.x, av1.y), pack_h2(av1.z, av1.w));
                *(uint4*)(&smu[st ^ 1][soff]) = stv;
            }
            cp_wait<0>();
        }
        __syncthreads();
    }

    // ---------------- epilogue ----------------
    const int eg = lane >> 2, tig = lane & 3;
    const float aggs = WAGG ? (1.0f + __ldg(&eps_arr[eps_idx])) : 0.f;
    float*  Cf = (float*)Cout;
    __half* Ch = (__half*)Cout;
    #pragma unroll
    for (int j = 0; j < 8; j++) {
        const int cb = col0 + wn * 64 + j * 8 + tig * 2;
        const float2 bi = *(const float2*)(bias + cb);
        float2 bs = make_float2(0.f, 0.f), bt = make_float2(0.f, 0.f);
        if (EPI == 2) { bs = *(const float2*)(bns + cb); bt = *(const float2*)(bnb + cb); }
        #pragma unroll
        for (int i = 0; i < 2; i++) {
            const int r0 = row0 + wm * 32 + i * 16 + eg;
            float4 v = acc[i][j];
            float2 lo = make_float2(v.x + bi.x, v.y + bi.y);
            float2 hi = make_float2(v.z + bi.x, v.w + bi.y);
            if (EPI >= 1) {
                lo.x = fmaxf(lo.x, 0.f); lo.y = fmaxf(lo.y, 0.f);
                hi.x = fmaxf(hi.x, 0.f); hi.y = fmaxf(hi.y, 0.f);
            }
            if (EPI == 2) {
                lo.x = fmaf(lo.x, bs.x, bt.x); lo.y = fmaf(lo.y, bs.y, bt.y);
                hi.x = fmaf(hi.x, bs.x, bt.x); hi.y = fmaf(hi.y, bs.y, bt.y);
            }
            if (r0 < M) {
                if (CH) *(__half2*)(Ch + (size_t)r0 * Ntotal + cb) = __floats2half2_rn(lo.x, lo.y);
                else {
                    *(float2*)(Cf + (size_t)r0 * Ntotal + cb) = lo;
                    if (WAGG)
                        *(float2*)(aggout + (size_t)r0 * Ntotal + cb) =
                            make_float2(lo.x * aggs, lo.y * aggs);
                }
            }
            if (r0 + 8 < M) {
                if (CH) *(__half2*)(Ch + (size_t)(r0 + 8) * Ntotal + cb) = __floats2half2_rn(hi.x, hi.y);
                else {
                    *(float2*)(Cf + (size_t)(r0 + 8) * Ntotal + cb) = hi;
                    if (WAGG)
                        *(float2*)(aggout + (size_t)(r0 + 8) * Ntotal + cb) =
                            make_float2(hi.x * aggs, hi.y * aggs);
                }
            }
        }
    }
}

// ---------------- launcher ----------------
extern "C" void kernel_launch(void* const* d_in, const int* in_sizes, int n_in,
                              void* d_out, int out_size)
{
    const float* x     = (const float*)d_in[0];
    const void*  ei    = d_in[1];
    const void*  batch = d_in[2];
    const float* w1    = (const float*)d_in[3];
    const float* b1    = (const float*)d_in[4];
    const float* w2    = (const float*)d_in[5];
    const float* b2    = (const float*)d_in[6];
    const float* eps   = (const float*)d_in[7];
    const float* bng   = (const float*)d_in[8];
    const float* bnbt  = (const float*)d_in[9];
    const float* bnm   = (const float*)d_in[10];
    const float* bnv   = (const float*)d_in[11];
    const float* wp1   = (const float*)d_in[12];
    const float* bp1   = (const float*)d_in[13];
    const float* wp2   = (const float*)d_in[14];
    const float* bp2   = (const float*)d_in[15];
    float* out = (float*)d_out;

    float *agg, *h, *pool, *cnt, *p1, *bns, *bnb;
    __half* th;
    uint4 *wf1, *wf2, *wfp1, *wfp2;
    cudaGetSymbolAddress((void**)&agg,  g_agg);
    cudaGetSymbolAddress((void**)&h,    g_h);
    cudaGetSymbolAddress((void**)&th,   g_th);
    cudaGetSymbolAddress((void**)&pool, g_pool);
    cudaGetSymbolAddress((void**)&cnt,  g_cnt);
    cudaGetSymbolAddress((void**)&p1,   g_p1);
    cudaGetSymbolAddress((void**)&bns,  g_bns);
    cudaGetSymbolAddress((void**)&bnb,  g_bnb);
    cudaGetSymbolAddress((void**)&wf1,  g_wf1);
    cudaGetSymbolAddress((void**)&wf2,  g_wf2);
    cudaGetSymbolAddress((void**)&wfp1, g_wfp1);
    cudaGetSymbolAddress((void**)&wfp2, g_wfp2);

    detect_idx<<<1, 1>>>((const unsigned int*)ei);
    bn_precompute<<<(5 * D + 255) / 256, 256>>>(bng, bnbt, bnm, bnv);
    for (int l = 0; l < LGIN; l++) {
        prep_wh<<<(D * HID2 / 8 + 255) / 256, 256>>>(w1 + (size_t)l * D * HID2,
                                                     wf1 + (size_t)l * D * HID2 / 8, D, HID2);
        prep_wh<<<(HID2 * D / 8 + 255) / 256, 256>>>(w2 + (size_t)l * HID2 * D,
                                                     wf2 + (size_t)l * HID2 * D / 8, HID2, D);
    }
    prep_wh<<<(D * NHID / 8 + 255) / 256, 256>>>(wp1, wfp1, D, NHID);
    prep_wh<<<(NHID * NOUT / 8 + 255) / 256, 256>>>(wp2, wfp2, NHID, NOUT);

    const int bnidx[4] = {0, 0, 1, 2};   // reference's bn-index bug, kept

    const int elem_blocks   = (NN * D / 4 + 255) / 256;
    const int edge_blocks   = (int)(((size_t)NE * 32 + 255) / 256);
    const int node_blocks   = (int)(((size_t)NN * 32 + 255) / 256);
    const int poolv4_blocks = (NG * D / 4 + 255) / 256;
    const int mtiles = (NN + 127) / 128;

    init_agg<<<elem_blocks, 256>>>(agg, x, eps, 0);

    for (int l = 0; l < LGIN; l++) {
        const float* hin = (l == 0) ? x : h;
        scatter_edges<<<edge_blocks, 256>>>(agg, hin, ei);
        // t(fp16) = relu(agg @ W1 + b1)   [NN, 512]
        hgemm<1, false, false, true><<<dim3(HID2 / 256, mtiles), 512>>>(
            agg, wf1 + (size_t)l * D * HID2 / 8, b1 + (size_t)l * HID2, th,
            NN, D, HID2, nullptr, nullptr, nullptr, nullptr, 0);
        // h = BN(relu(t @ W2 + b2)) [NN, 256]; layers 0-2 also emit agg=(1+eps[l+1])*h
        if (l < LGIN - 1) {
            hgemm<2, true, true, false><<<dim3(D / 256, mtiles), 512>>>(
                th, wf2 + (size_t)l * HID2 * D / 8, b2 + (size_t)l * D, h,
                NN, HID2, D, bns + bnidx[l] * D, bnb + bnidx[l] * D, agg, eps, l + 1);
        } else {
            hgemm<2, false, true, false><<<dim3(D / 256, mtiles), 512>>>(
                th, wf2 + (size_t)l * HID2 * D / 8, b2 + (size_t)l * D, h,
                NN, HID2, D, bns + bnidx[l] * D, bnb + bnidx[l] * D, nullptr, nullptr, 0);
        }
    }

    zero_pool<<<poolv4_blocks, 256>>>(pool, cnt);
    pool_scatter<<<node_blocks, 256>>>(pool, cnt, h, batch);
    normalize_pool<<<poolv4_blocks, 256>>>(pool, cnt);

    hgemm<1, false, false, false><<<dim3(NHID / 256, NG / 128), 512>>>(
        pool, wfp1, bp1, p1, NG, D, NHID, nullptr, nullptr, nullptr, nullptr, 0);
    hgemm<0, false, false, false><<<dim3(NOUT / 256, NG / 128), 512>>>(
        p1, wfp2, bp2, out, NG, NHID, NOUT, nullptr, nullptr, nullptr, nullptr, 0);
}

// round 9
// speedup vs baseline: 1.0883x; 1.0883x over previous
#include <cuda_runtime.h>
#include <cuda_fp16.h>
#include <cstdint>

#define DEV_INLINE __device__ __forceinline__

// ---------------- problem constants ----------------
constexpr int NN   = 100000;
constexpr int NE   = 300000;
constexpr int D    = 256;
constexpr int HID2 = 512;
constexpr int NHID = 512;
constexpr int NOUT = 768;
constexpr int NG   = 4096;
constexpr int LGIN = 4;

// ---------------- scratch (device globals) ----------------
__device__ float  g_agg [(size_t)NN * D];
__device__ float  g_h   [(size_t)NN * D];
__device__ __half g_th  [(size_t)NN * HID2];   // GIN hidden, fp16
__device__ float  g_pool[(size_t)NG * D];
__device__ float  g_cnt [NG];
__device__ float  g_p1  [(size_t)NG * NHID];
__device__ float  g_bns [5 * D];
__device__ float  g_bnb [5 * D];
__device__ int    g_is64;
// fragment-order fp16 weights (uint4 = 8 halves), 128-col blocks
__device__ uint4  g_wf1 [(size_t)LGIN * D * HID2 / 8];
__device__ uint4  g_wf2 [(size_t)LGIN * HID2 * D / 8];
__device__ uint4  g_wfp1[(size_t)D * NHID / 8];
__device__ uint4  g_wfp2[(size_t)NHID * NOUT / 8];

// ---------------- PTX helpers ----------------
DEV_INLINE void red_add_v4(float* p, float4 v) {
    asm volatile("red.global.add.v4.f32 [%0], {%1, %2, %3, %4};"
                 :: "l"(p), "f"(v.x), "f"(v.y), "f"(v.z), "f"(v.w) : "memory");
}
DEV_INLINE long long load_index(const void* base, long long i, int is64) {
    if (is64) return ((const long long*)base)[i];
    return (long long)((const int*)base)[i];
}
DEV_INLINE uint32_t smem_u32(const void* p) {
    uint32_t a;
    asm("{ .reg .u64 t; cvta.to.shared.u64 t, %1; cvt.u32.u64 %0, t; }" : "=r"(a) : "l"(p));
    return a;
}
DEV_INLINE void cp_async16s(uint32_t saddr, const void* g) {
    asm volatile("cp.async.cg.shared.global [%0], [%1], 16;" :: "r"(saddr), "l"(g) : "memory");
}
DEV_INLINE void cp_commit() { asm volatile("cp.async.commit_group;" ::: "memory"); }
template<int Nq> DEV_INLINE void cp_wait() { asm volatile("cp.async.wait_group %0;" :: "n"(Nq) : "memory"); }

DEV_INLINE uint32_t pack_h2(float a, float b) {
    __half2 h = __floats2half2_rn(a, b);
    return *(uint32_t*)&h;
}
DEV_INLINE void mma_f16(float4& c, uint32_t a0, uint32_t a1, uint32_t a2, uint32_t a3,
                        uint32_t b0, uint32_t b1) {
    asm volatile(
        "mma.sync.aligned.m16n8k16.row.col.f32.f16.f16.f32 "
        "{%0,%1,%2,%3}, {%4,%5,%6,%7}, {%8,%9}, {%0,%1,%2,%3};"
        : "+f"(c.x), "+f"(c.y), "+f"(c.z), "+f"(c.w)
        : "r"(a0), "r"(a1), "r"(a2), "r"(a3), "r"(b0), "r"(b1));
}

// ---------------- small kernels ----------------
__global__ void detect_idx(const unsigned int* __restrict__ w) {
    unsigned int nz = 0;
    #pragma unroll 1
    for (int k = 0; k < 256; k++) nz |= w[2 * k + 1];
    g_is64 = (nz == 0u) ? 1 : 0;
}

__global__ void bn_precompute(const float* __restrict__ gamma, const float* __restrict__ beta,
                              const float* __restrict__ mean,  const float* __restrict__ var) {
    int i = blockIdx.x * blockDim.x + threadIdx.x;
    if (i < 5 * D) {
        float s = gamma[i] * rsqrtf(var[i] + 1e-5f);
        g_bns[i] = s;
        g_bnb[i] = beta[i] - mean[i] * s;
    }
}

// Pack weight w[K][N] (row-major fp32) into fp16 m16n8k16 fragment order, 128-col blocks.
// uint4 id = ((nb*K16 + kt)*8 + p)*32 + lane covers n-tile pair (2p, 2p+1) of block nb.
__global__ void prep_wh(const float* __restrict__ src, uint4* __restrict__ dst, int K, int N) {
    int id = blockIdx.x * blockDim.x + threadIdx.x;
    int K16 = K >> 4;
    int total = (N >> 7) * K16 * 256;
    if (id >= total) return;
    int lane = id & 31;
    int p    = (id >> 5) & 7;
    int blk  = id >> 8;
    int kt   = blk % K16;
    int nb   = blk / K16;
    int g = lane >> 2, tig = lane & 3;
    int c0 = nb * 128 + p * 16 + g;
    int c1 = c0 + 8;
    int k0 = kt * 16 + tig * 2;
    uint32_t u0 = pack_h2(src[(size_t)k0 * N + c0],       src[(size_t)(k0 + 1) * N + c0]);
    uint32_t u1 = pack_h2(src[(size_t)(k0 + 8) * N + c0], src[(size_t)(k0 + 9) * N + c0]);
    uint32_t u2 = pack_h2(src[(size_t)k0 * N + c1],       src[(size_t)(k0 + 1) * N + c1]);
    uint32_t u3 = pack_h2(src[(size_t)(k0 + 8) * N + c1], src[(size_t)(k0 + 9) * N + c1]);
    dst[id] = make_uint4(u0, u1, u2, u3);
}

__global__ void init_agg(float* __restrict__ agg, const float* __restrict__ hin,
                         const float* __restrict__ eps_arr, int l) {
    size_t i = (size_t)blockIdx.x * blockDim.x + threadIdx.x;
    if (i < (size_t)NN * D / 4) {
        float s = 1.0f + __ldg(&eps_arr[l]);
        float4 v = ((const float4*)hin)[i];
        v.x *= s; v.y *= s; v.z *= s; v.w *= s;
        ((float4*)agg)[i] = v;
    }
}

__global__ void scatter_edges(float* __restrict__ agg, const float* __restrict__ h,
                              const void* __restrict__ ei) {
    int wid = (int)(((size_t)blockIdx.x * blockDim.x + threadIdx.x) >> 5);
    if (wid >= NE) return;
    int lane = threadIdx.x & 31;
    int is64 = g_is64;
    long long s = load_index(ei, wid, is64);
    long long d = load_index(ei, (long long)NE + wid, is64);
    const float4* hs = (const float4*)(h + (size_t)s * D);
    float*        ad = agg + (size_t)d * D;
    float4 v0 = __ldg(hs + lane);
    float4 v1 = __ldg(hs + 32 + lane);
    red_add_v4(ad + lane * 4,       v0);
    red_add_v4(ad + 128 + lane * 4, v1);
}

__global__ void pool_scatter(float* __restrict__ pool, float* __restrict__ cnt,
                             const float* __restrict__ h, const void* __restrict__ batch) {
    int wid = (int)(((size_t)blockIdx.x * blockDim.x + threadIdx.x) >> 5);
    if (wid >= NN) return;
    int lane = threadIdx.x & 31;
    long long g = load_index(batch, wid, g_is64);
    const float4* hs = (const float4*)(h + (size_t)wid * D);
    float*        pd = pool + (size_t)g * D;
    float4 v0 = __ldg(hs + lane);
    float4 v1 = __ldg(hs + 32 + lane);
    red_add_v4(pd + lane * 4,       v0);
    red_add_v4(pd + 128 + lane * 4, v1);
    if (lane == 0) atomicAdd(&cnt[g], 1.0f);
}

__global__ void zero_pool(float* __restrict__ pool, float* __restrict__ cnt) {
    int i = blockIdx.x * blockDim.x + threadIdx.x;
    if (i < NG * D / 4) ((float4*)pool)[i] = make_float4(0.f, 0.f, 0.f, 0.f);
    if (i < NG) cnt[i] = 0.f;
}

__global__ void normalize_pool(float* __restrict__ pool, const float* __restrict__ cnt) {
    int i = blockIdx.x * blockDim.x + threadIdx.x;
    if (i < NG * D / 4) {
        int g = i >> 6;
        float s = 1.0f / fmaxf(__ldg(&cnt[g]), 1.0f);
        float4 v = ((float4*)pool)[i];
        v.x *= s; v.y *= s; v.z *= s; v.w *= s;
        ((float4*)pool)[i] = v;
    }
}

// ---------------- fp16 mma.sync GEMM, 128x128 CTA tile, 2 CTAs/SM ----------------
// 8 warps as 4(m) x 2(n), warp tile 32x64, m16n8k16, fp32 accum.
// SMEM per stage (u32): A [8 mt][4 reg][32 lane] = 1024, B [8 p][32 lane] uint4 = 1024.
template<int EPI, bool WAGG, bool AH, bool CH>
__global__ __launch_bounds__(256, 2)
void hgemm(const void* __restrict__ Ain, const uint4* __restrict__ Wf,
           const float* __restrict__ bias, void* __restrict__ Cout,
           int M, int K, int Ntotal,
           const float* __restrict__ bns, const float* __restrict__ bnb,
           float* __restrict__ aggout, const float* __restrict__ eps_arr, int eps_idx)
{
    __shared__ uint32_t smu[2][2048];

    const int tid  = threadIdx.x;
    const int w    = tid >> 5, lane = tid & 31;
    const int wm   = w >> 1,   wn   = w & 1;        // 4 x 2 warp grid
    const int row0 = blockIdx.y * 128;
    const int col0 = blockIdx.x * 128;
    const int K16  = K >> 4;

    // A producer mapping: row rr, k-half kk8
    const int rr   = tid >> 1;
    const int kk8  = tid & 1;
    const int mt   = rr >> 4;
    const int g    = rr & 7;
    const int reg  = ((rr >> 3) & 1) + 2 * kk8;
    const int soff = mt * 128 + reg * 32 + g * 4;
    int rrg = row0 + rr; if (rrg > M - 1) rrg = M - 1;

    const __half* Ah = (const __half*)Ain;
    const float*  Af = (const float*)Ain;
    const uint4*  Bsrc = Wf + (size_t)blockIdx.x * K16 * 256;

    float4 acc[2][8];
    #pragma unroll
    for (int i = 0; i < 2; i++)
        #pragma unroll
        for (int j = 0; j < 8; j++) acc[i][j] = make_float4(0.f, 0.f, 0.f, 0.f);

    uint4  avh;
    float4 av0, av1;

    // prologue: stage 0
    {
        if (AH) avh = *(const uint4*)(Ah + (size_t)rrg * K + kk8 * 8);
        else { const float4* p = (const float4*)(Af + (size_t)rrg * K + kk8 * 8);
               av0 = __ldg(p); av1 = __ldg(p + 1); }
        cp_async16s(smem_u32(&smu[0][1024 + tid * 4]), Bsrc + tid);   // 256 uint4 = B stage
        cp_commit();
        uint4 st;
        if (AH) st = avh;
        else st = make_uint4(pack_h2(av0.x, av0.y), pack_h2(av0.z, av0.w),
                             pack_h2(av1.x, av1.y), pack_h2(av1.z, av1.w));
        *(uint4*)(&smu[0][soff]) = st;
        cp_wait<0>();
        __syncthreads();
    }

    for (int kt = 0; kt < K16; kt++) {
        const int st = kt & 1;
        const bool hn = (kt + 1) < K16;
        if (hn) {
            if (AH) avh = *(const uint4*)(Ah + (size_t)rrg * K + (kt + 1) * 16 + kk8 * 8);
            else { const float4* p = (const float4*)(Af + (size_t)rrg * K + (kt + 1) * 16 + kk8 * 8);
                   av0 = __ldg(p); av1 = __ldg(p + 1); }
            cp_async16s(smem_u32(&smu[st ^ 1][1024 + tid * 4]), Bsrc + (size_t)(kt + 1) * 256 + tid);
            cp_commit();
        }
        // ---- compute stage st ----
        const uint32_t* sA = smu[st];
        const uint32_t* sB = smu[st] + 1024;
        uint4 b[4];
        #pragma unroll
        for (int jp = 0; jp < 4; jp++)
            b[jp] = *(const uint4*)(sB + ((wn * 4 + jp) * 32 + lane) * 4);
        #pragma unroll
        for (int i = 0; i < 2; i++) {
            const uint32_t* ab = sA + (wm * 2 + i) * 128 + lane;
            uint32_t a0 = ab[0], a1 = ab[32], a2 = ab[64], a3 = ab[96];
            #pragma unroll
            for (int jp = 0; jp < 4; jp++) {
                mma_f16(acc[i][jp * 2],     a0, a1, a2, a3, b[jp].x, b[jp].y);
                mma_f16(acc[i][jp * 2 + 1], a0, a1, a2, a3, b[jp].z, b[jp].w);
            }
        }
        if (hn) {
            uint4 stv;
            if (AH) stv = avh;
            else stv = make_uint4(pack_h2(av0.x, av0.y), pack_h2(av0.z, av0.w),
                                  pack_h2(av1.x, av1.y), pack_h2(av1.z, av1.w));
            *(uint4*)(&smu[st ^ 1][soff]) = stv;
            cp_wait<0>();
        }
        __syncthreads();
    }

    // ---------------- epilogue ----------------
    const int eg = lane >> 2, tig = lane & 3;
    const float aggs = WAGG ? (1.0f + __ldg(&eps_arr[eps_idx])) : 0.f;
    float*  Cf = (float*)Cout;
    __half* Ch = (__half*)Cout;
    #pragma unroll
    for (int j = 0; j < 8; j++) {
        const int cb = col0 + wn * 64 + j * 8 + tig * 2;
        const float2 bi = *(const float2*)(bias + cb);
        float2 bs = make_float2(0.f, 0.f), bt = make_float2(0.f, 0.f);
        if (EPI == 2) { bs = *(const float2*)(bns + cb); bt = *(const float2*)(bnb + cb); }
        #pragma unroll
        for (int i = 0; i < 2; i++) {
            const int r0 = row0 + wm * 32 + i * 16 + eg;
            float4 v = acc[i][j];
            float2 lo = make_float2(v.x + bi.x, v.y + bi.y);
            float2 hi = make_float2(v.z + bi.x, v.w + bi.y);
            if (EPI >= 1) {
                lo.x = fmaxf(lo.x, 0.f); lo.y = fmaxf(lo.y, 0.f);
                hi.x = fmaxf(hi.x, 0.f); hi.y = fmaxf(hi.y, 0.f);
            }
            if (EPI == 2) {
                lo.x = fmaf(lo.x, bs.x, bt.x); lo.y = fmaf(lo.y, bs.y, bt.y);
                hi.x = fmaf(hi.x, bs.x, bt.x); hi.y = fmaf(hi.y, bs.y, bt.y);
            }
            if (r0 < M) {
                if (CH) *(__half2*)(Ch + (size_t)r0 * Ntotal + cb) = __floats2half2_rn(lo.x, lo.y);
                else {
                    *(float2*)(Cf + (size_t)r0 * Ntotal + cb) = lo;
                    if (WAGG)
                        *(float2*)(aggout + (size_t)r0 * Ntotal + cb) =
                            make_float2(lo.x * aggs, lo.y * aggs);
                }
            }
            if (r0 + 8 < M) {
                if (CH) *(__half2*)(Ch + (size_t)(r0 + 8) * Ntotal + cb) = __floats2half2_rn(hi.x, hi.y);
                else {
                    *(float2*)(Cf + (size_t)(r0 + 8) * Ntotal + cb) = hi;
                    if (WAGG)
                        *(float2*)(aggout + (size_t)(r0 + 8) * Ntotal + cb) =
                            make_float2(hi.x * aggs, hi.y * aggs);
                }
            }
        }
    }
}

// ---------------- launcher ----------------
extern "C" void kernel_launch(void* const* d_in, const int* in_sizes, int n_in,
                              void* d_out, int out_size)
{
    const float* x     = (const float*)d_in[0];
    const void*  ei    = d_in[1];
    const void*  batch = d_in[2];
    const float* w1    = (const float*)d_in[3];
    const float* b1    = (const float*)d_in[4];
    const float* w2    = (const float*)d_in[5];
    const float* b2    = (const float*)d_in[6];
    const float* eps   = (const float*)d_in[7];
    const float* bng   = (const float*)d_in[8];
    const float* bnbt  = (const float*)d_in[9];
    const float* bnm   = (const float*)d_in[10];
    const float* bnv   = (const float*)d_in[11];
    const float* wp1   = (const float*)d_in[12];
    const float* bp1   = (const float*)d_in[13];
    const float* wp2   = (const float*)d_in[14];
    const float* bp2   = (const float*)d_in[15];
    float* out = (float*)d_out;

    float *agg, *h, *pool, *cnt, *p1, *bns, *bnb;
    __half* th;
    uint4 *wf1, *wf2, *wfp1, *wfp2;
    cudaGetSymbolAddress((void**)&agg,  g_agg);
    cudaGetSymbolAddress((void**)&h,    g_h);
    cudaGetSymbolAddress((void**)&th,   g_th);
    cudaGetSymbolAddress((void**)&pool, g_pool);
    cudaGetSymbolAddress((void**)&cnt,  g_cnt);
    cudaGetSymbolAddress((void**)&p1,   g_p1);
    cudaGetSymbolAddress((void**)&bns,  g_bns);
    cudaGetSymbolAddress((void**)&bnb,  g_bnb);
    cudaGetSymbolAddress((void**)&wf1,  g_wf1);
    cudaGetSymbolAddress((void**)&wf2,  g_wf2);
    cudaGetSymbolAddress((void**)&wfp1, g_wfp1);
    cudaGetSymbolAddress((void**)&wfp2, g_wfp2);

    detect_idx<<<1, 1>>>((const unsigned int*)ei);
    bn_precompute<<<(5 * D + 255) / 256, 256>>>(bng, bnbt, bnm, bnv);
    for (int l = 0; l < LGIN; l++) {
        prep_wh<<<(D * HID2 / 8 + 255) / 256, 256>>>(w1 + (size_t)l * D * HID2,
                                                     wf1 + (size_t)l * D * HID2 / 8, D, HID2);
        prep_wh<<<(HID2 * D / 8 + 255) / 256, 256>>>(w2 + (size_t)l * HID2 * D,
                                                     wf2 + (size_t)l * HID2 * D / 8, HID2, D);
    }
    prep_wh<<<(D * NHID / 8 + 255) / 256, 256>>>(wp1, wfp1, D, NHID);
    prep_wh<<<(NHID * NOUT / 8 + 255) / 256, 256>>>(wp2, wfp2, NHID, NOUT);

    const int bnidx[4] = {0, 0, 1, 2};   // reference's bn-index bug, kept

    const int elem_blocks   = (NN * D / 4 + 255) / 256;
    const int edge_blocks   = (int)(((size_t)NE * 32 + 255) / 256);
    const int node_blocks   = (int)(((size_t)NN * 32 + 255) / 256);
    const int poolv4_blocks = (NG * D / 4 + 255) / 256;
    const int mtiles = (NN + 127) / 128;

    init_agg<<<elem_blocks, 256>>>(agg, x, eps, 0);

    for (int l = 0; l < LGIN; l++) {
        const float* hin = (l == 0) ? x : h;
        scatter_edges<<<edge_blocks, 256>>>(agg, hin, ei);
        // t(fp16) = relu(agg @ W1 + b1)   [NN, 512]
        hgemm<1, false, false, true><<<dim3(HID2 / 128, mtiles), 256>>>(
            agg, wf1 + (size_t)l * D * HID2 / 8, b1 + (size_t)l * HID2, th,
            NN, D, HID2, nullptr, nullptr, nullptr, nullptr, 0);
        // h = BN(relu(t @ W2 + b2)) [NN, 256]; layers 0-2 also emit agg=(1+eps[l+1])*h
        if (l < LGIN - 1) {
            hgemm<2, true, true, false><<<dim3(D / 128, mtiles), 256>>>(
                th, wf2 + (size_t)l * HID2 * D / 8, b2 + (size_t)l * D, h,
                NN, HID2, D, bns + bnidx[l] * D, bnb + bnidx[l] * D, agg, eps, l + 1);
        } else {
            hgemm<2, false, true, false><<<dim3(D / 128, mtiles), 256>>>(
                th, wf2 + (size_t)l * HID2 * D / 8, b2 + (size_t)l * D, h,
                NN, HID2, D, bns + bnidx[l] * D, bnb + bnidx[l] * D, nullptr, nullptr, 0);
        }
    }

    zero_pool<<<poolv4_blocks, 256>>>(pool, cnt);
    pool_scatter<<<node_blocks, 256>>>(pool, cnt, h, batch);
    normalize_pool<<<poolv4_blocks, 256>>>(pool, cnt);

    hgemm<1, false, false, false><<<dim3(NHID / 128, NG / 128), 256>>>(
        pool, wfp1, bp1, p1, NG, D, NHID, nullptr, nullptr, nullptr, nullptr, 0);
    hgemm<0, false, false, false><<<dim3(NOUT / 128, NG / 128), 256>>>(
        p1, wfp2, bp2, out, NG, NHID, NOUT, nullptr, nullptr, nullptr, nullptr, 0);
}

// round 10
// speedup vs baseline: 1.3235x; 1.2161x over previous
#include <cuda_runtime.h>
#include <cuda_fp16.h>
#include <cstdint>

#define DEV_INLINE __device__ __forceinline__

// ---------------- problem constants ----------------
constexpr int NN   = 100000;
constexpr int NE   = 300000;
constexpr int D    = 256;
constexpr int HID2 = 512;
constexpr int NHID = 512;
constexpr int NOUT = 768;
constexpr int NG   = 4096;
constexpr int LGIN = 4;
constexpr int SCAN_BLKS = (NN + 1023) / 1024;   // 98

// ---------------- scratch (device globals) ----------------
__device__ __half g_aggh[(size_t)NN * D];      // aggregated features, fp16
__device__ float  g_h   [(size_t)NN * D];      // layer output, fp32
__device__ __half g_th  [(size_t)NN * HID2];   // GIN hidden, fp16
__device__ float  g_pool[(size_t)NG * D];
__device__ float  g_cnt [NG];
__device__ float  g_p1  [(size_t)NG * NHID];
__device__ float  g_bns [5 * D];
__device__ float  g_bnb [5 * D];
__device__ int    g_is64;
// CSR (built per launch)
__device__ int    g_deg [NN];                  // histogram, then reused as fill cursor
__device__ int    g_off [NN + 1];
__device__ int    g_col [NE];
__device__ int    g_bsum[SCAN_BLKS];
// fragment-order fp16 weights (uint4 = 8 halves), 128-col blocks
__device__ uint4  g_wf1 [(size_t)LGIN * D * HID2 / 8];
__device__ uint4  g_wf2 [(size_t)LGIN * HID2 * D / 8];
__device__ uint4  g_wfp1[(size_t)D * NHID / 8];
__device__ uint4  g_wfp2[(size_t)NHID * NOUT / 8];

// ---------------- PTX helpers ----------------
DEV_INLINE void red_add_v4(float* p, float4 v) {
    asm volatile("red.global.add.v4.f32 [%0], {%1, %2, %3, %4};"
                 :: "l"(p), "f"(v.x), "f"(v.y), "f"(v.z), "f"(v.w) : "memory");
}
DEV_INLINE long long load_index(const void* base, long long i, int is64) {
    if (is64) return ((const long long*)base)[i];
    return (long long)((const int*)base)[i];
}
DEV_INLINE uint32_t smem_u32(const void* p) {
    uint32_t a;
    asm("{ .reg .u64 t; cvta.to.shared.u64 t, %1; cvt.u32.u64 %0, t; }" : "=r"(a) : "l"(p));
    return a;
}
DEV_INLINE void cp_async16s(uint32_t saddr, const void* g) {
    asm volatile("cp.async.cg.shared.global [%0], [%1], 16;" :: "r"(saddr), "l"(g) : "memory");
}
DEV_INLINE void cp_commit() { asm volatile("cp.async.commit_group;" ::: "memory"); }
template<int Nq> DEV_INLINE void cp_wait() { asm volatile("cp.async.wait_group %0;" :: "n"(Nq) : "memory"); }

DEV_INLINE uint32_t pack_h2(float a, float b) {
    __half2 h = __floats2half2_rn(a, b);
    return *(uint32_t*)&h;
}
DEV_INLINE void mma_f16(float4& c, uint32_t a0, uint32_t a1, uint32_t a2, uint32_t a3,
                        uint32_t b0, uint32_t b1) {
    asm volatile(
        "mma.sync.aligned.m16n8k16.row.col.f32.f16.f16.f32 "
        "{%0,%1,%2,%3}, {%4,%5,%6,%7}, {%8,%9}, {%0,%1,%2,%3};"
        : "+f"(c.x), "+f"(c.y), "+f"(c.z), "+f"(c.w)
        : "r"(a0), "r"(a1), "r"(a2), "r"(a3), "r"(b0), "r"(b1));
}

// ---------------- small kernels ----------------
__global__ void detect_idx(const unsigned int* __restrict__ w) {
    unsigned int nz = 0;
    #pragma unroll 1
    for (int k = 0; k < 256; k++) nz |= w[2 * k + 1];
    g_is64 = (nz == 0u) ? 1 : 0;
}

__global__ void bn_precompute(const float* __restrict__ gamma, const float* __restrict__ beta,
                              const float* __restrict__ mean,  const float* __restrict__ var) {
    int i = blockIdx.x * blockDim.x + threadIdx.x;
    if (i < 5 * D) {
        float s = gamma[i] * rsqrtf(var[i] + 1e-5f);
        g_bns[i] = s;
        g_bnb[i] = beta[i] - mean[i] * s;
    }
}

// Pack weight w[K][N] (row-major fp32) into fp16 m16n8k16 fragment order, 128-col blocks.
__global__ void prep_wh(const float* __restrict__ src, uint4* __restrict__ dst, int K, int N) {
    int id = blockIdx.x * blockDim.x + threadIdx.x;
    int K16 = K >> 4;
    int total = (N >> 7) * K16 * 256;
    if (id >= total) return;
    int lane = id & 31;
    int p    = (id >> 5) & 7;
    int blk  = id >> 8;
    int kt   = blk % K16;
    int nb   = blk / K16;
    int g = lane >> 2, tig = lane & 3;
    int c0 = nb * 128 + p * 16 + g;
    int c1 = c0 + 8;
    int k0 = kt * 16 + tig * 2;
    uint32_t u0 = pack_h2(src[(size_t)k0 * N + c0],       src[(size_t)(k0 + 1) * N + c0]);
    uint32_t u1 = pack_h2(src[(size_t)(k0 + 8) * N + c0], src[(size_t)(k0 + 9) * N + c0]);
    uint32_t u2 = pack_h2(src[(size_t)k0 * N + c1],       src[(size_t)(k0 + 1) * N + c1]);
    uint32_t u3 = pack_h2(src[(size_t)(k0 + 8) * N + c1], src[(size_t)(k0 + 9) * N + c1]);
    dst[id] = make_uint4(u0, u1, u2, u3);
}

// ---------------- CSR build ----------------
__global__ void csr_zero(int* __restrict__ a) {
    int i = blockIdx.x * blockDim.x + threadIdx.x;
    if (i < NN) a[i] = 0;
}
__global__ void csr_hist(const void* __restrict__ ei, int* __restrict__ deg) {
    int e = blockIdx.x * blockDim.x + threadIdx.x;
    if (e < NE) {
        int d = (int)load_index(ei, (long long)NE + e, g_is64);
        atomicAdd(&deg[d], 1);
    }
}
__global__ void csr_scan1(const int* __restrict__ deg, int* __restrict__ off,
                          int* __restrict__ bsum) {
    __shared__ int sm[1024];
    int t = threadIdx.x;
    int i = blockIdx.x * 1024 + t;
    sm[t] = (i < NN) ? deg[i] : 0;
    __syncthreads();
    #pragma unroll
    for (int d = 1; d < 1024; d <<= 1) {
        int v = sm[t];
        if (t >= d) v += sm[t - d];
        __syncthreads();
        sm[t] = v;
        __syncthreads();
    }
    if (i < NN) off[i + 1] = sm[t];
    if (t == 1023) bsum[blockIdx.x] = sm[1023];
}
__global__ void csr_scan2(int* __restrict__ bsum) {
    __shared__ int sm[SCAN_BLKS];
    int t = threadIdx.x;
    if (t < SCAN_BLKS) sm[t] = bsum[t];
    __syncthreads();
    if (t == 0) {
        int run = 0;
        for (int i = 0; i < SCAN_BLKS; i++) { int v = sm[i]; sm[i] = run; run += v; }
    }
    __syncthreads();
    if (t < SCAN_BLKS) bsum[t] = sm[t];
}
__global__ void csr_scan3(int* __restrict__ off, const int* __restrict__ bsum) {
    int i = blockIdx.x * blockDim.x + threadIdx.x;
    if (i < NN) off[i + 1] += bsum[i >> 10];
    if (i == 0) off[0] = 0;
}
__global__ void csr_fill(const void* __restrict__ ei, const int* __restrict__ off,
                         int* __restrict__ cur, int* __restrict__ col) {
    int e = blockIdx.x * blockDim.x + threadIdx.x;
    if (e < NE) {
        int is64 = g_is64;
        int s = (int)load_index(ei, e, is64);
        int d = (int)load_index(ei, (long long)NE + e, is64);
        int p = atomicAdd(&cur[d], 1);
        col[off[d] + p] = s;
    }
}

// ---------------- aggregation: aggh[n] = fp16( (1+eps)*h[n] + sum_{src in CSR[n]} h[src] ) ----------------
__global__ void aggregate(__half* __restrict__ aggh, const float* __restrict__ h,
                          const int* __restrict__ off, const int* __restrict__ col,
                          const float* __restrict__ eps_arr, int l) {
    int n = (int)(((size_t)blockIdx.x * blockDim.x + threadIdx.x) >> 5);
    if (n >= NN) return;
    int lane = threadIdx.x & 31;
    float s = 1.0f + __ldg(&eps_arr[l]);
    const float4* hp = (const float4*)(h + (size_t)n * D);
    float4 a0 = __ldg(hp + lane);
    float4 a1 = __ldg(hp + 32 + lane);
    a0.x *= s; a0.y *= s; a0.z *= s; a0.w *= s;
    a1.x *= s; a1.y *= s; a1.z *= s; a1.w *= s;
    int b = __ldg(&off[n]), e = __ldg(&off[n + 1]);
    for (int j = b; j < e; j++) {
        int src = __ldg(&col[j]);
        const float4* p = (const float4*)(h + (size_t)src * D);
        float4 v0 = __ldg(p + lane);
        float4 v1 = __ldg(p + 32 + lane);
        a0.x += v0.x; a0.y += v0.y; a0.z += v0.z; a0.w += v0.w;
        a1.x += v1.x; a1.y += v1.y; a1.z += v1.z; a1.w += v1.w;
    }
    uint2 o0 = make_uint2(pack_h2(a0.x, a0.y), pack_h2(a0.z, a0.w));
    uint2 o1 = make_uint2(pack_h2(a1.x, a1.y), pack_h2(a1.z, a1.w));
    __half* row = aggh + (size_t)n * D;
    *(uint2*)(row + lane * 4)       = o0;
    *(uint2*)(row + 128 + lane * 4) = o1;
}

__global__ void pool_scatter(float* __restrict__ pool, float* __restrict__ cnt,
                             const float* __restrict__ h, const void* __restrict__ batch) {
    int wid = (int)(((size_t)blockIdx.x * blockDim.x + threadIdx.x) >> 5);
    if (wid >= NN) return;
    int lane = threadIdx.x & 31;
    long long g = load_index(batch, wid, g_is64);
    const float4* hs = (const float4*)(h + (size_t)wid * D);
    float*        pd = pool + (size_t)g * D;
    float4 v0 = __ldg(hs + lane);
    float4 v1 = __ldg(hs + 32 + lane);
    red_add_v4(pd + lane * 4,       v0);
    red_add_v4(pd + 128 + lane * 4, v1);
    if (lane == 0) atomicAdd(&cnt[g], 1.0f);
}

__global__ void zero_pool(float* __restrict__ pool, float* __restrict__ cnt) {
    int i = blockIdx.x * blockDim.x + threadIdx.x;
    if (i < NG * D / 4) ((float4*)pool)[i] = make_float4(0.f, 0.f, 0.f, 0.f);
    if (i < NG) cnt[i] = 0.f;
}

__global__ void normalize_pool(float* __restrict__ pool, const float* __restrict__ cnt) {
    int i = blockIdx.x * blockDim.x + threadIdx.x;
    if (i < NG * D / 4) {
        int g = i >> 6;
        float s = 1.0f / fmaxf(__ldg(&cnt[g]), 1.0f);
        float4 v = ((float4*)pool)[i];
        v.x *= s; v.y *= s; v.z *= s; v.w *= s;
        ((float4*)pool)[i] = v;
    }
}

// ---------------- fp16 mma.sync GEMM, 128x128 CTA tile, 2 CTAs/SM ----------------
// 8 warps as 4(m) x 2(n), warp tile 32x64, m16n8k16, fp32 accum.
template<int EPI, bool AH, bool CH>
__global__ __launch_bounds__(256, 2)
void hgemm(const void* __restrict__ Ain, const uint4* __restrict__ Wf,
           const float* __restrict__ bias, void* __restrict__ Cout,
           int M, int K, int Ntotal,
           const float* __restrict__ bns, const float* __restrict__ bnb)
{
    __shared__ uint32_t smu[2][2048];

    const int tid  = threadIdx.x;
    const int w    = tid >> 5, lane = tid & 31;
    const int wm   = w >> 1,   wn   = w & 1;
    const int row0 = blockIdx.y * 128;
    const int col0 = blockIdx.x * 128;
    const int K16  = K >> 4;

    const int rr   = tid >> 1;
    const int kk8  = tid & 1;
    const int mt   = rr >> 4;
    const int g    = rr & 7;
    const int reg  = ((rr >> 3) & 1) + 2 * kk8;
    const int soff = mt * 128 + reg * 32 + g * 4;
    int rrg = row0 + rr; if (rrg > M - 1) rrg = M - 1;

    const __half* Ah = (const __half*)Ain;
    const float*  Af = (const float*)Ain;
    const uint4*  Bsrc = Wf + (size_t)blockIdx.x * K16 * 256;

    float4 acc[2][8];
    #pragma unroll
    for (int i = 0; i < 2; i++)
        #pragma unroll
        for (int j = 0; j < 8; j++) acc[i][j] = make_float4(0.f, 0.f, 0.f, 0.f);

    uint4  avh;
    float4 av0, av1;

    {   // prologue
        if (AH) avh = *(const uint4*)(Ah + (size_t)rrg * K + kk8 * 8);
        else { const float4* p = (const float4*)(Af + (size_t)rrg * K + kk8 * 8);
               av0 = __ldg(p); av1 = __ldg(p + 1); }
        cp_async16s(smem_u32(&smu[0][1024 + tid * 4]), Bsrc + tid);
        cp_commit();
        uint4 st;
        if (AH) st = avh;
        else st = make_uint4(pack_h2(av0.x, av0.y), pack_h2(av0.z, av0.w),
                             pack_h2(av1.x, av1.y), pack_h2(av1.z, av1.w));
        *(uint4*)(&smu[0][soff]) = st;
        cp_wait<0>();
        __syncthreads();
    }

    for (int kt = 0; kt < K16; kt++) {
        const int st = kt & 1;
        const bool hn = (kt + 1) < K16;
        if (hn) {
            if (AH) avh = *(const uint4*)(Ah + (size_t)rrg * K + (kt + 1) * 16 + kk8 * 8);
            else { const float4* p = (const float4*)(Af + (size_t)rrg * K + (kt + 1) * 16 + kk8 * 8);
                   av0 = __ldg(p); av1 = __ldg(p + 1); }
            cp_async16s(smem_u32(&smu[st ^ 1][1024 + tid * 4]), Bsrc + (size_t)(kt + 1) * 256 + tid);
            cp_commit();
        }
        const uint32_t* sA = smu[st];
        const uint32_t* sB = smu[st] + 1024;
        uint4 b[4];
        #pragma unroll
        for (int jp = 0; jp < 4; jp++)
            b[jp] = *(const uint4*)(sB + ((wn * 4 + jp) * 32 + lane) * 4);
        #pragma unroll
        for (int i = 0; i < 2; i++) {
            const uint32_t* ab = sA + (wm * 2 + i) * 128 + lane;
            uint32_t a0 = ab[0], a1 = ab[32], a2 = ab[64], a3 = ab[96];
            #pragma unroll
            for (int jp = 0; jp < 4; jp++) {
                mma_f16(acc[i][jp * 2],     a0, a1, a2, a3, b[jp].x, b[jp].y);
                mma_f16(acc[i][jp * 2 + 1], a0, a1, a2, a3, b[jp].z, b[jp].w);
            }
        }
        if (hn) {
            uint4 stv;
            if (AH) stv = avh;
            else stv = make_uint4(pack_h2(av0.x, av0.y), pack_h2(av0.z, av0.w),
                                  pack_h2(av1.x, av1.y), pack_h2(av1.z, av1.w));
            *(uint4*)(&smu[st ^ 1][soff]) = stv;
            cp_wait<0>();
        }
        __syncthreads();
    }

    // ---------------- epilogue ----------------
    const int eg = lane >> 2, tig = lane & 3;
    float*  Cf = (float*)Cout;
    __half* Ch = (__half*)Cout;
    #pragma unroll
    for (int j = 0; j < 8; j++) {
        const int cb = col0 + wn * 64 + j * 8 + tig * 2;
        const float2 bi = *(const float2*)(bias + cb);
        float2 bs = make_float2(0.f, 0.f), bt = make_float2(0.f, 0.f);
        if (EPI == 2) { bs = *(const float2*)(bns + cb); bt = *(const float2*)(bnb + cb); }
        #pragma unroll
        for (int i = 0; i < 2; i++) {
            const int r0 = row0 + wm * 32 + i * 16 + eg;
            float4 v = acc[i][j];
            float2 lo = make_float2(v.x + bi.x, v.y + bi.y);
            float2 hi = make_float2(v.z + bi.x, v.w + bi.y);
            if (EPI >= 1) {
                lo.x = fmaxf(lo.x, 0.f); lo.y = fmaxf(lo.y, 0.f);
                hi.x = fmaxf(hi.x, 0.f); hi.y = fmaxf(hi.y, 0.f);
            }
            if (EPI == 2) {
                lo.x = fmaf(lo.x, bs.x, bt.x); lo.y = fmaf(lo.y, bs.y, bt.y);
                hi.x = fmaf(hi.x, bs.x, bt.x); hi.y = fmaf(hi.y, bs.y, bt.y);
            }
            if (r0 < M) {
                if (CH) *(__half2*)(Ch + (size_t)r0 * Ntotal + cb) = __floats2half2_rn(lo.x, lo.y);
                else    *(float2*)(Cf + (size_t)r0 * Ntotal + cb) = lo;
            }
            if (r0 + 8 < M) {
                if (CH) *(__half2*)(Ch + (size_t)(r0 + 8) * Ntotal + cb) = __floats2half2_rn(hi.x, hi.y);
                else    *(float2*)(Cf + (size_t)(r0 + 8) * Ntotal + cb) = hi;
            }
        }
    }
}

// ---------------- launcher ----------------
extern "C" void kernel_launch(void* const* d_in, const int* in_sizes, int n_in,
                              void* d_out, int out_size)
{
    const float* x     = (const float*)d_in[0];
    const void*  ei    = d_in[1];
    const void*  batch = d_in[2];
    const float* w1    = (const float*)d_in[3];
    const float* b1    = (const float*)d_in[4];
    const float* w2    = (const float*)d_in[5];
    const float* b2    = (const float*)d_in[6];
    const float* eps   = (const float*)d_in[7];
    const float* bng   = (const float*)d_in[8];
    const float* bnbt  = (const float*)d_in[9];
    const float* bnm   = (const float*)d_in[10];
    const float* bnv   = (const float*)d_in[11];
    const float* wp1   = (const float*)d_in[12];
    const float* bp1   = (const float*)d_in[13];
    const float* wp2   = (const float*)d_in[14];
    const float* bp2   = (const float*)d_in[15];
    float* out = (float*)d_out;

    float *h, *pool, *cnt, *p1, *bns, *bnb;
    __half *th, *aggh;
    int *deg, *off, *col, *bsum;
    uint4 *wf1, *wf2, *wfp1, *wfp2;
    cudaGetSymbolAddress((void**)&aggh, g_aggh);
    cudaGetSymbolAddress((void**)&h,    g_h);
    cudaGetSymbolAddress((void**)&th,   g_th);
    cudaGetSymbolAddress((void**)&pool, g_pool);
    cudaGetSymbolAddress((void**)&cnt,  g_cnt);
    cudaGetSymbolAddress((void**)&p1,   g_p1);
    cudaGetSymbolAddress((void**)&bns,  g_bns);
    cudaGetSymbolAddress((void**)&bnb,  g_bnb);
    cudaGetSymbolAddress((void**)&deg,  g_deg);
    cudaGetSymbolAddress((void**)&off,  g_off);
    cudaGetSymbolAddress((void**)&col,  g_col);
    cudaGetSymbolAddress((void**)&bsum, g_bsum);
    cudaGetSymbolAddress((void**)&wf1,  g_wf1);
    cudaGetSymbolAddress((void**)&wf2,  g_wf2);
    cudaGetSymbolAddress((void**)&wfp1, g_wfp1);
    cudaGetSymbolAddress((void**)&wfp2, g_wfp2);

    detect_idx<<<1, 1>>>((const unsigned int*)ei);
    bn_precompute<<<(5 * D + 255) / 256, 256>>>(bng, bnbt, bnm, bnv);
    for (int l = 0; l < LGIN; l++) {
        prep_wh<<<(D * HID2 / 8 + 255) / 256, 256>>>(w1 + (size_t)l * D * HID2,
                                                     wf1 + (size_t)l * D * HID2 / 8, D, HID2);
        prep_wh<<<(HID2 * D / 8 + 255) / 256, 256>>>(w2 + (size_t)l * HID2 * D,
                                                     wf2 + (size_t)l * HID2 * D / 8, HID2, D);
    }
    prep_wh<<<(D * NHID / 8 + 255) / 256, 256>>>(wp1, wfp1, D, NHID);
    prep_wh<<<(NHID * NOUT / 8 + 255) / 256, 256>>>(wp2, wfp2, NHID, NOUT);

    // ---- CSR build ----
    const int nnb = (NN + 255) / 256, neb = (NE + 255) / 256;
    csr_zero<<<nnb, 256>>>(deg);
    csr_hist<<<neb, 256>>>(ei, deg);
    csr_scan1<<<SCAN_BLKS, 1024>>>(deg, off, bsum);
    csr_scan2<<<1, 128>>>(bsum);
    csr_scan3<<<nnb, 256>>>(off, bsum);
    csr_zero<<<nnb, 256>>>(deg);                 // reuse as fill cursor
    csr_fill<<<neb, 256>>>(ei, off, deg, col);

    const int bnidx[4] = {0, 0, 1, 2};           // reference's bn-index bug, kept
    const int node_blocks   = (int)(((size_t)NN * 32 + 255) / 256);
    const int poolv4_blocks = (NG * D / 4 + 255) / 256;
    const int mtiles = (NN + 127) / 128;

    for (int l = 0; l < LGIN; l++) {
        const float* hin = (l == 0) ? x : h;
        aggregate<<<node_blocks, 256>>>(aggh, hin, off, col, eps, l);
        // t(fp16) = relu(aggh @ W1 + b1)   [NN, 512]
        hgemm<1, true, true><<<dim3(HID2 / 128, mtiles), 256>>>(
            aggh, wf1 + (size_t)l * D * HID2 / 8, b1 + (size_t)l * HID2, th,
            NN, D, HID2, nullptr, nullptr);
        // h(fp32) = BN(relu(t @ W2 + b2))  [NN, 256]
        hgemm<2, true, false><<<dim3(D / 128, mtiles), 256>>>(
            th, wf2 + (size_t)l * HID2 * D / 8, b2 + (size_t)l * D, h,
            NN, HID2, D, bns + bnidx[l] * D, bnb + bnidx[l] * D);
    }

    zero_pool<<<poolv4_blocks, 256>>>(pool, cnt);
    pool_scatter<<<node_blocks, 256>>>(pool, cnt, h, batch);
    normalize_pool<<<poolv4_blocks, 256>>>(pool, cnt);

    hgemm<1, false, false><<<dim3(NHID / 128, NG / 128), 256>>>(
        pool, wfp1, bp1, p1, NG, D, NHID, nullptr, nullptr);
    hgemm<0, false, false><<<dim3(NOUT / 128, NG / 128), 256>>>(
        p1, wfp2, bp2, out, NG, NHID, NOUT, nullptr, nullptr);
}

// round 11
// speedup vs baseline: 1.3705x; 1.0355x over previous
#include <cuda_runtime.h>
#include <cuda_fp16.h>
#include <cstdint>

#define DEV_INLINE __device__ __forceinline__

// ---------------- problem constants ----------------
constexpr int NN   = 100000;
constexpr int NE   = 300000;
constexpr int D    = 256;
constexpr int HID2 = 512;
constexpr int NHID = 512;
constexpr int NOUT = 768;
constexpr int NG   = 4096;
constexpr int LGIN = 4;
constexpr int SCAN_BLKS = (NN + 1023) / 1024;   // 98

// ---------------- scratch (device globals) ----------------
__device__ __half g_aggh[(size_t)NN * D];      // aggregated features, fp16
__device__ __half g_h   [(size_t)NN * D];      // layer output, fp16 (fits L2!)
__device__ __half g_th  [(size_t)NN * HID2];   // GIN hidden, fp16
__device__ float  g_pool[(size_t)NG * D];
__device__ float  g_cnt [NG];
__device__ float  g_p1  [(size_t)NG * NHID];
__device__ float  g_bns [5 * D];
__device__ float  g_bnb [5 * D];
__device__ int    g_is64;
// CSR (built per launch)
__device__ int    g_deg [NN];
__device__ int    g_off [NN + 1];
__device__ int    g_col [NE];
__device__ int    g_bsum[SCAN_BLKS];
// fragment-order fp16 weights (uint4 = 8 halves), 128-col blocks
__device__ uint4  g_wf1 [(size_t)LGIN * D * HID2 / 8];
__device__ uint4  g_wf2 [(size_t)LGIN * HID2 * D / 8];
__device__ uint4  g_wfp1[(size_t)D * NHID / 8];
__device__ uint4  g_wfp2[(size_t)NHID * NOUT / 8];

// ---------------- PTX helpers ----------------
DEV_INLINE void red_add_v4(float* p, float4 v) {
    asm volatile("red.global.add.v4.f32 [%0], {%1, %2, %3, %4};"
                 :: "l"(p), "f"(v.x), "f"(v.y), "f"(v.z), "f"(v.w) : "memory");
}
DEV_INLINE long long load_index(const void* base, long long i, int is64) {
    if (is64) return ((const long long*)base)[i];
    return (long long)((const int*)base)[i];
}
DEV_INLINE uint32_t smem_u32(const void* p) {
    uint32_t a;
    asm("{ .reg .u64 t; cvta.to.shared.u64 t, %1; cvt.u32.u64 %0, t; }" : "=r"(a) : "l"(p));
    return a;
}
DEV_INLINE void cp_async16s(uint32_t saddr, const void* g) {
    asm volatile("cp.async.cg.shared.global [%0], [%1], 16;" :: "r"(saddr), "l"(g) : "memory");
}
DEV_INLINE void cp_commit() { asm volatile("cp.async.commit_group;" ::: "memory"); }
template<int Nq> DEV_INLINE void cp_wait() { asm volatile("cp.async.wait_group %0;" :: "n"(Nq) : "memory"); }

DEV_INLINE uint32_t pack_h2(float a, float b) {
    __half2 h = __floats2half2_rn(a, b);
    return *(uint32_t*)&h;
}
DEV_INLINE void unpack8(uint4 v, float* f) {
    float2 f0 = __half22float2(*(__half2*)&v.x);
    float2 f1 = __half22float2(*(__half2*)&v.y);
    float2 f2 = __half22float2(*(__half2*)&v.z);
    float2 f3 = __half22float2(*(__half2*)&v.w);
    f[0] = f0.x; f[1] = f0.y; f[2] = f1.x; f[3] = f1.y;
    f[4] = f2.x; f[5] = f2.y; f[6] = f3.x; f[7] = f3.y;
}
DEV_INLINE void mma_f16(float4& c, uint32_t a0, uint32_t a1, uint32_t a2, uint32_t a3,
                        uint32_t b0, uint32_t b1) {
    asm volatile(
        "mma.sync.aligned.m16n8k16.row.col.f32.f16.f16.f32 "
        "{%0,%1,%2,%3}, {%4,%5,%6,%7}, {%8,%9}, {%0,%1,%2,%3};"
        : "+f"(c.x), "+f"(c.y), "+f"(c.z), "+f"(c.w)
        : "r"(a0), "r"(a1), "r"(a2), "r"(a3), "r"(b0), "r"(b1));
}

// ---------------- small kernels ----------------
__global__ void detect_idx(const unsigned int* __restrict__ w) {
    unsigned int nz = 0;
    #pragma unroll 1
    for (int k = 0; k < 256; k++) nz |= w[2 * k + 1];
    g_is64 = (nz == 0u) ? 1 : 0;
}

__global__ void bn_precompute(const float* __restrict__ gamma, const float* __restrict__ beta,
                              const float* __restrict__ mean,  const float* __restrict__ var) {
    int i = blockIdx.x * blockDim.x + threadIdx.x;
    if (i < 5 * D) {
        float s = gamma[i] * rsqrtf(var[i] + 1e-5f);
        g_bns[i] = s;
        g_bnb[i] = beta[i] - mean[i] * s;
    }
}

// Pack weight w[K][N] (row-major fp32) into fp16 m16n8k16 fragment order, 128-col blocks.
__global__ void prep_wh(const float* __restrict__ src, uint4* __restrict__ dst, int K, int N) {
    int id = blockIdx.x * blockDim.x + threadIdx.x;
    int K16 = K >> 4;
    int total = (N >> 7) * K16 * 256;
    if (id >= total) return;
    int lane = id & 31;
    int p    = (id >> 5) & 7;
    int blk  = id >> 8;
    int kt   = blk % K16;
    int nb   = blk / K16;
    int g = lane >> 2, tig = lane & 3;
    int c0 = nb * 128 + p * 16 + g;
    int c1 = c0 + 8;
    int k0 = kt * 16 + tig * 2;
    uint32_t u0 = pack_h2(src[(size_t)k0 * N + c0],       src[(size_t)(k0 + 1) * N + c0]);
    uint32_t u1 = pack_h2(src[(size_t)(k0 + 8) * N + c0], src[(size_t)(k0 + 9) * N + c0]);
    uint32_t u2 = pack_h2(src[(size_t)k0 * N + c1],       src[(size_t)(k0 + 1) * N + c1]);
    uint32_t u3 = pack_h2(src[(size_t)(k0 + 8) * N + c1], src[(size_t)(k0 + 9) * N + c1]);
    dst[id] = make_uint4(u0, u1, u2, u3);
}

// ---------------- CSR build ----------------
__global__ void csr_zero(int* __restrict__ a) {
    int i = blockIdx.x * blockDim.x + threadIdx.x;
    if (i < NN) a[i] = 0;
}
__global__ void csr_hist(const void* __restrict__ ei, int* __restrict__ deg) {
    int e = blockIdx.x * blockDim.x + threadIdx.x;
    if (e < NE) {
        int d = (int)load_index(ei, (long long)NE + e, g_is64);
        atomicAdd(&deg[d], 1);
    }
}
__global__ void csr_scan1(const int* __restrict__ deg, int* __restrict__ off,
                          int* __restrict__ bsum) {
    __shared__ int sm[1024];
    int t = threadIdx.x;
    int i = blockIdx.x * 1024 + t;
    sm[t] = (i < NN) ? deg[i] : 0;
    __syncthreads();
    #pragma unroll
    for (int d = 1; d < 1024; d <<= 1) {
        int v = sm[t];
        if (t >= d) v += sm[t - d];
        __syncthreads();
        sm[t] = v;
        __syncthreads();
    }
    if (i < NN) off[i + 1] = sm[t];
    if (t == 1023) bsum[blockIdx.x] = sm[1023];
}
__global__ void csr_scan2(int* __restrict__ bsum) {
    __shared__ int sm[SCAN_BLKS];
    int t = threadIdx.x;
    if (t < SCAN_BLKS) sm[t] = bsum[t];
    __syncthreads();
    if (t == 0) {
        int run = 0;
        for (int i = 0; i < SCAN_BLKS; i++) { int v = sm[i]; sm[i] = run; run += v; }
    }
    __syncthreads();
    if (t < SCAN_BLKS) bsum[t] = sm[t];
}
__global__ void csr_scan3(int* __restrict__ off, const int* __restrict__ bsum) {
    int i = blockIdx.x * blockDim.x + threadIdx.x;
    if (i < NN) off[i + 1] += bsum[i >> 10];
    if (i == 0) off[0] = 0;
}
__global__ void csr_fill(const void* __restrict__ ei, const int* __restrict__ off,
                         int* __restrict__ cur, int* __restrict__ col) {
    int e = blockIdx.x * blockDim.x + threadIdx.x;
    if (e < NE) {
        int is64 = g_is64;
        int s = (int)load_index(ei, e, is64);
        int d = (int)load_index(ei, (long long)NE + e, is64);
        int p = atomicAdd(&cur[d], 1);
        col[off[d] + p] = s;
    }
}

// ---------------- aggregation: aggh[n] = fp16( (1+eps)*h[n] + sum_{src} h[src] ) ----------------
// HIN16: input rows are fp16 (layers 1..3); else fp32 (layer 0 reads x).
template<bool HIN16>
__global__ void aggregate(__half* __restrict__ aggh, const void* __restrict__ hin,
                          const int* __restrict__ off, const int* __restrict__ col,
                          const float* __restrict__ eps_arr, int l) {
    int n = (int)(((size_t)blockIdx.x * blockDim.x + threadIdx.x) >> 5);
    if (n >= NN) return;
    int lane = threadIdx.x & 31;
    float s = 1.0f + __ldg(&eps_arr[l]);
    float a[8];
    if (HIN16) {
        uint4 v = *(const uint4*)((const __half*)hin + (size_t)n * D + lane * 8);
        unpack8(v, a);
    } else {
        const float4* p = (const float4*)((const float*)hin + (size_t)n * D + lane * 8);
        float4 v0 = __ldg(p), v1 = __ldg(p + 1);
        a[0] = v0.x; a[1] = v0.y; a[2] = v0.z; a[3] = v0.w;
        a[4] = v1.x; a[5] = v1.y; a[6] = v1.z; a[7] = v1.w;
    }
    #pragma unroll
    for (int k = 0; k < 8; k++) a[k] *= s;
    int b = __ldg(&off[n]), e = __ldg(&off[n + 1]);
    for (int j = b; j < e; j++) {
        int src = __ldg(&col[j]);
        float t[8];
        if (HIN16) {
            uint4 v = *(const uint4*)((const __half*)hin + (size_t)src * D + lane * 8);
            unpack8(v, t);
        } else {
            const float4* p = (const float4*)((const float*)hin + (size_t)src * D + lane * 8);
            float4 v0 = __ldg(p), v1 = __ldg(p + 1);
            t[0] = v0.x; t[1] = v0.y; t[2] = v0.z; t[3] = v0.w;
            t[4] = v1.x; t[5] = v1.y; t[6] = v1.z; t[7] = v1.w;
        }
        #pragma unroll
        for (int k = 0; k < 8; k++) a[k] += t[k];
    }
    uint4 o = make_uint4(pack_h2(a[0], a[1]), pack_h2(a[2], a[3]),
                         pack_h2(a[4], a[5]), pack_h2(a[6], a[7]));
    *(uint4*)(aggh + (size_t)n * D + lane * 8) = o;
}

__global__ void pool_scatter(float* __restrict__ pool, float* __restrict__ cnt,
                             const __half* __restrict__ h, const void* __restrict__ batch) {
    int wid = (int)(((size_t)blockIdx.x * blockDim.x + threadIdx.x) >> 5);
    if (wid >= NN) return;
    int lane = threadIdx.x & 31;
    long long g = load_index(batch, wid, g_is64);
    uint4 v = *(const uint4*)(h + (size_t)wid * D + lane * 8);
    float f[8];
    unpack8(v, f);
    float* pd = pool + (size_t)g * D + lane * 8;
    red_add_v4(pd,     make_float4(f[0], f[1], f[2], f[3]));
    red_add_v4(pd + 4, make_float4(f[4], f[5], f[6], f[7]));
    if (lane == 0) atomicAdd(&cnt[g], 1.0f);
}

__global__ void zero_pool(float* __restrict__ pool, float* __restrict__ cnt) {
    int i = blockIdx.x * blockDim.x + threadIdx.x;
    if (i < NG * D / 4) ((float4*)pool)[i] = make_float4(0.f, 0.f, 0.f, 0.f);
    if (i < NG) cnt[i] = 0.f;
}

__global__ void normalize_pool(float* __restrict__ pool, const float* __restrict__ cnt) {
    int i = blockIdx.x * blockDim.x + threadIdx.x;
    if (i < NG * D / 4) {
        int g = i >> 6;
        float s = 1.0f / fmaxf(__ldg(&cnt[g]), 1.0f);
        float4 v = ((float4*)pool)[i];
        v.x *= s; v.y *= s; v.z *= s; v.w *= s;
        ((float4*)pool)[i] = v;
    }
}

// ---------------- fp16 mma.sync GEMM, 128x128 CTA tile, 2 CTAs/SM ----------------
template<int EPI, bool AH, bool CH>
__global__ __launch_bounds__(256, 2)
void hgemm(const void* __restrict__ Ain, const uint4* __restrict__ Wf,
           const float* __restrict__ bias, void* __restrict__ Cout,
           int M, int K, int Ntotal,
           const float* __restrict__ bns, const float* __restrict__ bnb)
{
    __shared__ uint32_t smu[2][2048];

    const int tid  = threadIdx.x;
    const int w    = tid >> 5, lane = tid & 31;
    const int wm   = w >> 1,   wn   = w & 1;
    const int row0 = blockIdx.y * 128;
    const int col0 = blockIdx.x * 128;
    const int K16  = K >> 4;

    const int rr   = tid >> 1;
    const int kk8  = tid & 1;
    const int mt   = rr >> 4;
    const int g    = rr & 7;
    const int reg  = ((rr >> 3) & 1) + 2 * kk8;
    const int soff = mt * 128 + reg * 32 + g * 4;
    int rrg = row0 + rr; if (rrg > M - 1) rrg = M - 1;

    const __half* Ah = (const __half*)Ain;
    const float*  Af = (const float*)Ain;
    const uint4*  Bsrc = Wf + (size_t)blockIdx.x * K16 * 256;

    float4 acc[2][8];
    #pragma unroll
    for (int i = 0; i < 2; i++)
        #pragma unroll
        for (int j = 0; j < 8; j++) acc[i][j] = make_float4(0.f, 0.f, 0.f, 0.f);

    uint4  avh;
    float4 av0, av1;

    {   // prologue
        if (AH) avh = *(const uint4*)(Ah + (size_t)rrg * K + kk8 * 8);
        else { const float4* p = (const float4*)(Af + (size_t)rrg * K + kk8 * 8);
               av0 = __ldg(p); av1 = __ldg(p + 1); }
        cp_async16s(smem_u32(&smu[0][1024 + tid * 4]), Bsrc + tid);
        cp_commit();
        uint4 st;
        if (AH) st = avh;
        else st = make_uint4(pack_h2(av0.x, av0.y), pack_h2(av0.z, av0.w),
                             pack_h2(av1.x, av1.y), pack_h2(av1.z, av1.w));
        *(uint4*)(&smu[0][soff]) = st;
        cp_wait<0>();
        __syncthreads();
    }

    for (int kt = 0; kt < K16; kt++) {
        const int st = kt & 1;
        const bool hn = (kt + 1) < K16;
        if (hn) {
            if (AH) avh = *(const uint4*)(Ah + (size_t)rrg * K + (kt + 1) * 16 + kk8 * 8);
            else { const float4* p = (const float4*)(Af + (size_t)rrg * K + (kt + 1) * 16 + kk8 * 8);
                   av0 = __ldg(p); av1 = __ldg(p + 1); }
            cp_async16s(smem_u32(&smu[st ^ 1][1024 + tid * 4]), Bsrc + (size_t)(kt + 1) * 256 + tid);
            cp_commit();
        }
        const uint32_t* sA = smu[st];
        const uint32_t* sB = smu[st] + 1024;
        uint4 b[4];
        #pragma unroll
        for (int jp = 0; jp < 4; jp++)
            b[jp] = *(const uint4*)(sB + ((wn * 4 + jp) * 32 + lane) * 4);
        #pragma unroll
        for (int i = 0; i < 2; i++) {
            const uint32_t* ab = sA + (wm * 2 + i) * 128 + lane;
            uint32_t a0 = ab[0], a1 = ab[32], a2 = ab[64], a3 = ab[96];
            #pragma unroll
            for (int jp = 0; jp < 4; jp++) {
                mma_f16(acc[i][jp * 2],     a0, a1, a2, a3, b[jp].x, b[jp].y);
                mma_f16(acc[i][jp * 2 + 1], a0, a1, a2, a3, b[jp].z, b[jp].w);
            }
        }
        if (hn) {
            uint4 stv;
            if (AH) stv = avh;
            else stv = make_uint4(pack_h2(av0.x, av0.y), pack_h2(av0.z, av0.w),
                                  pack_h2(av1.x, av1.y), pack_h2(av1.z, av1.w));
            *(uint4*)(&smu[st ^ 1][soff]) = stv;
            cp_wait<0>();
        }
        __syncthreads();
    }

    // ---------------- epilogue ----------------
    const int eg = lane >> 2, tig = lane & 3;
    float*  Cf = (float*)Cout;
    __half* Ch = (__half*)Cout;
    #pragma unroll
    for (int j = 0; j < 8; j++) {
        const int cb = col0 + wn * 64 + j * 8 + tig * 2;
        const float2 bi = *(const float2*)(bias + cb);
        float2 bs = make_float2(0.f, 0.f), bt = make_float2(0.f, 0.f);
        if (EPI == 2) { bs = *(const float2*)(bns + cb); bt = *(const float2*)(bnb + cb); }
        #pragma unroll
        for (int i = 0; i < 2; i++) {
            const int r0 = row0 + wm * 32 + i * 16 + eg;
            float4 v = acc[i][j];
            float2 lo = make_float2(v.x + bi.x, v.y + bi.y);
            float2 hi = make_float2(v.z + bi.x, v.w + bi.y);
            if (EPI >= 1) {
                lo.x = fmaxf(lo.x, 0.f); lo.y = fmaxf(lo.y, 0.f);
                hi.x = fmaxf(hi.x, 0.f); hi.y = fmaxf(hi.y, 0.f);
            }
            if (EPI == 2) {
                lo.x = fmaf(lo.x, bs.x, bt.x); lo.y = fmaf(lo.y, bs.y, bt.y);
                hi.x = fmaf(hi.x, bs.x, bt.x); hi.y = fmaf(hi.y, bs.y, bt.y);
            }
            if (r0 < M) {
                if (CH) *(__half2*)(Ch + (size_t)r0 * Ntotal + cb) = __floats2half2_rn(lo.x, lo.y);
                else    *(float2*)(Cf + (size_t)r0 * Ntotal + cb) = lo;
            }
            if (r0 + 8 < M) {
                if (CH) *(__half2*)(Ch + (size_t)(r0 + 8) * Ntotal + cb) = __floats2half2_rn(hi.x, hi.y);
                else    *(float2*)(Cf + (size_t)(r0 + 8) * Ntotal + cb) = hi;
            }
        }
    }
}

// ---------------- launcher ----------------
extern "C" void kernel_launch(void* const* d_in, const int* in_sizes, int n_in,
                              void* d_out, int out_size)
{
    const float* x     = (const float*)d_in[0];
    const void*  ei    = d_in[1];
    const void*  batch = d_in[2];
    const float* w1    = (const float*)d_in[3];
    const float* b1    = (const float*)d_in[4];
    const float* w2    = (const float*)d_in[5];
    const float* b2    = (const float*)d_in[6];
    const float* eps   = (const float*)d_in[7];
    const float* bng   = (const float*)d_in[8];
    const float* bnbt  = (const float*)d_in[9];
    const float* bnm   = (const float*)d_in[10];
    const float* bnv   = (const float*)d_in[11];
    const float* wp1   = (const float*)d_in[12];
    const float* bp1   = (const float*)d_in[13];
    const float* wp2   = (const float*)d_in[14];
    const float* bp2   = (const float*)d_in[15];
    float* out = (float*)d_out;

    float *pool, *cnt, *p1, *bns, *bnb;
    __half *th, *aggh, *h;
    int *deg, *off, *col, *bsum;
    uint4 *wf1, *wf2, *wfp1, *wfp2;
    cudaGetSymbolAddress((void**)&aggh, g_aggh);
    cudaGetSymbolAddress((void**)&h,    g_h);
    cudaGetSymbolAddress((void**)&th,   g_th);
    cudaGetSymbolAddress((void**)&pool, g_pool);
    cudaGetSymbolAddress((void**)&cnt,  g_cnt);
    cudaGetSymbolAddress((void**)&p1,   g_p1);
    cudaGetSymbolAddress((void**)&bns,  g_bns);
    cudaGetSymbolAddress((void**)&bnb,  g_bnb);
    cudaGetSymbolAddress((void**)&deg,  g_deg);
    cudaGetSymbolAddress((void**)&off,  g_off);
    cudaGetSymbolAddress((void**)&col,  g_col);
    cudaGetSymbolAddress((void**)&bsum, g_bsum);
    cudaGetSymbolAddress((void**)&wf1,  g_wf1);
    cudaGetSymbolAddress((void**)&wf2,  g_wf2);
    cudaGetSymbolAddress((void**)&wfp1, g_wfp1);
    cudaGetSymbolAddress((void**)&wfp2, g_wfp2);

    detect_idx<<<1, 1>>>((const unsigned int*)ei);
    bn_precompute<<<(5 * D + 255) / 256, 256>>>(bng, bnbt, bnm, bnv);
    for (int l = 0; l < LGIN; l++) {
        prep_wh<<<(D * HID2 / 8 + 255) / 256, 256>>>(w1 + (size_t)l * D * HID2,
                                                     wf1 + (size_t)l * D * HID2 / 8, D, HID2);
        prep_wh<<<(HID2 * D / 8 + 255) / 256, 256>>>(w2 + (size_t)l * HID2 * D,
                                                     wf2 + (size_t)l * HID2 * D / 8, HID2, D);
    }
    prep_wh<<<(D * NHID / 8 + 255) / 256, 256>>>(wp1, wfp1, D, NHID);
    prep_wh<<<(NHID * NOUT / 8 + 255) / 256, 256>>>(wp2, wfp2, NHID, NOUT);

    // ---- CSR build ----
    const int nnb = (NN + 255) / 256, neb = (NE + 255) / 256;
    csr_zero<<<nnb, 256>>>(deg);
    csr_hist<<<neb, 256>>>(ei, deg);
    csr_scan1<<<SCAN_BLKS, 1024>>>(deg, off, bsum);
    csr_scan2<<<1, 128>>>(bsum);
    csr_scan3<<<nnb, 256>>>(off, bsum);
    csr_zero<<<nnb, 256>>>(deg);
    csr_fill<<<neb, 256>>>(ei, off, deg, col);

    const int bnidx[4] = {0, 0, 1, 2};           // reference's bn-index bug, kept
    const int node_blocks   = (int)(((size_t)NN * 32 + 255) / 256);
    const int poolv4_blocks = (NG * D / 4 + 255) / 256;
    const int mtiles = (NN + 127) / 128;

    for (int l = 0; l < LGIN; l++) {
        if (l == 0) aggregate<false><<<node_blocks, 256>>>(aggh, x, off, col, eps, l);
        else        aggregate<true ><<<node_blocks, 256>>>(aggh, h, off, col, eps, l);
        // t(fp16) = relu(aggh @ W1 + b1)   [NN, 512]
        hgemm<1, true, true><<<dim3(HID2 / 128, mtiles), 256>>>(
            aggh, wf1 + (size_t)l * D * HID2 / 8, b1 + (size_t)l * HID2, th,
            NN, D, HID2, nullptr, nullptr);
        // h(fp16) = BN(relu(t @ W2 + b2))  [NN, 256]
        hgemm<2, true, true><<<dim3(D / 128, mtiles), 256>>>(
            th, wf2 + (size_t)l * HID2 * D / 8, b2 + (size_t)l * D, h,
            NN, HID2, D, bns + bnidx[l] * D, bnb + bnidx[l] * D);
    }

    zero_pool<<<poolv4_blocks, 256>>>(pool, cnt);
    pool_scatter<<<node_blocks, 256>>>(pool, cnt, h, batch);
    normalize_pool<<<poolv4_blocks, 256>>>(pool, cnt);

    hgemm<1, false, false><<<dim3(NHID / 128, NG / 128), 256>>>(
        pool, wfp1, bp1, p1, NG, D, NHID, nullptr, nullptr);
    hgemm<0, false, false><<<dim3(NOUT / 128, NG / 128), 256>>>(
        p1, wfp2, bp2, out, NG, NHID, NOUT, nullptr, nullptr);
}

// round 13
// speedup vs baseline: 1.5151x; 1.1055x over previous
#include <cuda_runtime.h>
#include <cuda_fp16.h>
#include <cstdint>

#define DEV_INLINE __device__ __forceinline__

// ---------------- problem constants ----------------
constexpr int NN   = 100000;
constexpr int NE   = 300000;
constexpr int D    = 256;
constexpr int HID2 = 512;
constexpr int NHID = 512;
constexpr int NOUT = 768;
constexpr int NG   = 4096;
constexpr int LGIN = 4;
constexpr int SCAN_BLKS = (NN + 1023) / 1024;

// ---------------- scratch (device globals) ----------------
__device__ __half g_aggh[(size_t)NN * D];
__device__ __half g_h   [(size_t)NN * D];
__device__ float  g_pool[(size_t)NG * D];
__device__ float  g_cnt [NG];
__device__ float  g_p1  [(size_t)NG * NHID];
__device__ float  g_bns [5 * D];
__device__ float  g_bnb [5 * D];
__device__ int    g_is64;
__device__ int    g_deg [NN];
__device__ int    g_off [NN + 1];
__device__ int    g_col [NE];
__device__ int    g_bsum[SCAN_BLKS];
__device__ uint4  g_wf1 [(size_t)LGIN * D * HID2 / 8];
__device__ uint4  g_wf2 [(size_t)LGIN * HID2 * D / 8];
__device__ uint4  g_wfp1[(size_t)D * NHID / 8];
__device__ uint4  g_wfp2[(size_t)NHID * NOUT / 8];

// ---------------- PTX helpers ----------------
DEV_INLINE void red_add_v4(float* p, float4 v) {
    asm volatile("red.global.add.v4.f32 [%0], {%1, %2, %3, %4};"
                 :: "l"(p), "f"(v.x), "f"(v.y), "f"(v.z), "f"(v.w) : "memory");
}
DEV_INLINE long long load_index(const void* base, long long i, int is64) {
    if (is64) return ((const long long*)base)[i];
    return (long long)((const int*)base)[i];
}
DEV_INLINE uint32_t smem_u32(const void* p) {
    uint32_t a;
    asm("{ .reg .u64 t; cvta.to.shared.u64 t, %1; cvt.u32.u64 %0, t; }" : "=r"(a) : "l"(p));
    return a;
}
DEV_INLINE void cp_async16s(uint32_t saddr, const void* g) {
    asm volatile("cp.async.cg.shared.global [%0], [%1], 16;" :: "r"(saddr), "l"(g) : "memory");
}
DEV_INLINE void cp_commit() { asm volatile("cp.async.commit_group;" ::: "memory"); }
template<int Nq> DEV_INLINE void cp_wait() { asm volatile("cp.async.wait_group %0;" :: "n"(Nq) : "memory"); }

DEV_INLINE uint32_t pack_h2(float a, float b) {
    __half2 h = __floats2half2_rn(a, b);
    return *(uint32_t*)&h;
}
DEV_INLINE void unpack8(uint4 v, float* f) {
    float2 f0 = __half22float2(*(__half2*)&v.x);
    float2 f1 = __half22float2(*(__half2*)&v.y);
    float2 f2 = __half22float2(*(__half2*)&v.z);
    float2 f3 = __half22float2(*(__half2*)&v.w);
    f[0] = f0.x; f[1] = f0.y; f[2] = f1.x; f[3] = f1.y;
    f[4] = f2.x; f[5] = f2.y; f[6] = f3.x; f[7] = f3.y;
}
DEV_INLINE void mma_f16(float4& c, uint32_t a0, uint32_t a1, uint32_t a2, uint32_t a3,
                        uint32_t b0, uint32_t b1) {
    asm volatile(
        "mma.sync.aligned.m16n8k16.row.col.f32.f16.f16.f32 "
        "{%0,%1,%2,%3}, {%4,%5,%6,%7}, {%8,%9}, {%0,%1,%2,%3};"
        : "+f"(c.x), "+f"(c.y), "+f"(c.z), "+f"(c.w)
        : "r"(a0), "r"(a1), "r"(a2), "r"(a3), "r"(b0), "r"(b1));
}

// ---------------- small kernels ----------------
__global__ void detect_idx(const unsigned int* __restrict__ w) {
    unsigned int nz = 0;
    #pragma unroll 1
    for (int k = 0; k < 256; k++) nz |= w[2 * k + 1];
    g_is64 = (nz == 0u) ? 1 : 0;
}

__global__ void bn_precompute(const float* __restrict__ gamma, const float* __restrict__ beta,
                              const float* __restrict__ mean,  const float* __restrict__ var) {
    int i = blockIdx.x * blockDim.x + threadIdx.x;
    if (i < 5 * D) {
        float s = gamma[i] * rsqrtf(var[i] + 1e-5f);
        g_bns[i] = s;
        g_bnb[i] = beta[i] - mean[i] * s;
    }
}

__global__ void prep_wh(const float* __restrict__ src, uint4* __restrict__ dst, int K, int N) {
    int id = blockIdx.x * blockDim.x + threadIdx.x;
    int K16 = K >> 4;
    int total = (N >> 7) * K16 * 256;
    if (id >= total) return;
    int lane = id & 31;
    int p    = (id >> 5) & 7;
    int blk  = id >> 8;
    int kt   = blk % K16;
    int nb   = blk / K16;
    int g = lane >> 2, tig = lane & 3;
    int c0 = nb * 128 + p * 16 + g;
    int c1 = c0 + 8;
    int k0 = kt * 16 + tig * 2;
    uint32_t u0 = pack_h2(src[(size_t)k0 * N + c0],       src[(size_t)(k0 + 1) * N + c0]);
    uint32_t u1 = pack_h2(src[(size_t)(k0 + 8) * N + c0], src[(size_t)(k0 + 9) * N + c0]);
    uint32_t u2 = pack_h2(src[(size_t)k0 * N + c1],       src[(size_t)(k0 + 1) * N + c1]);
    uint32_t u3 = pack_h2(src[(size_t)(k0 + 8) * N + c1], src[(size_t)(k0 + 9) * N + c1]);
    dst[id] = make_uint4(u0, u1, u2, u3);
}

// ---------------- CSR build ----------------
__global__ void csr_zero(int* __restrict__ a) {
    int i = blockIdx.x * blockDim.x + threadIdx.x;
    if (i < NN) a[i] = 0;
}
__global__ void csr_hist(const void* __restrict__ ei, int* __restrict__ deg) {
    int e = blockIdx.x * blockDim.x + threadIdx.x;
    if (e < NE) {
        int d = (int)load_index(ei, (long long)NE + e, g_is64);
        atomicAdd(&deg[d], 1);
    }
}
__global__ void csr_scan1(const int* __restrict__ deg, int* __restrict__ off,
                          int* __restrict__ bsum) {
    __shared__ int sm[1024];
    int t = threadIdx.x;
    int i = blockIdx.x * 1024 + t;
    sm[t] = (i < NN) ? deg[i] : 0;
    __syncthreads();
    #pragma unroll
    for (int d = 1; d < 1024; d <<= 1) {
        int v = sm[t];
        if (t >= d) v += sm[t - d];
        __syncthreads();
        sm[t] = v;
        __syncthreads();
    }
    if (i < NN) off[i + 1] = sm[t];
    if (t == 1023) bsum[blockIdx.x] = sm[1023];
}
__global__ void csr_scan2(int* __restrict__ bsum) {
    __shared__ int sm[SCAN_BLKS];
    int t = threadIdx.x;
    if (t < SCAN_BLKS) sm[t] = bsum[t];
    __syncthreads();
    if (t == 0) {
        int run = 0;
        for (int i = 0; i < SCAN_BLKS; i++) { int v = sm[i]; sm[i] = run; run += v; }
    }
    __syncthreads();
    if (t < SCAN_BLKS) bsum[t] = sm[t];
}
__global__ void csr_scan3(int* __restrict__ off, const int* __restrict__ bsum) {
    int i = blockIdx.x * blockDim.x + threadIdx.x;
    if (i < NN) off[i + 1] += bsum[i >> 10];
    if (i == 0) off[0] = 0;
}
__global__ void csr_fill(const void* __restrict__ ei, const int* __restrict__ off,
                         int* __restrict__ cur, int* __restrict__ col) {
    int e = blockIdx.x * blockDim.x + threadIdx.x;
    if (e < NE) {
        int is64 = g_is64;
        int s = (int)load_index(ei, e, is64);
        int d = (int)load_index(ei, (long long)NE + e, is64);
        int p = atomicAdd(&cur[d], 1);
        col[off[d] + p] = s;
    }
}

// ---------------- aggregation ----------------
template<bool HIN16>
__global__ void aggregate(__half* __restrict__ aggh, const void* __restrict__ hin,
                          const int* __restrict__ off, const int* __restrict__ col,
                          const float* __restrict__ eps_arr, int l) {
    int n = (int)(((size_t)blockIdx.x * blockDim.x + threadIdx.x) >> 5);
    if (n >= NN) return;
    int lane = threadIdx.x & 31;
    float s = 1.0f + __ldg(&eps_arr[l]);
    float a[8];
    if (HIN16) {
        uint4 v = *(const uint4*)((const __half*)hin + (size_t)n * D + lane * 8);
        unpack8(v, a);
    } else {
        const float4* p = (const float4*)((const float*)hin + (size_t)n * D + lane * 8);
        float4 v0 = __ldg(p), v1 = __ldg(p + 1);
        a[0] = v0.x; a[1] = v0.y; a[2] = v0.z; a[3] = v0.w;
        a[4] = v1.x; a[5] = v1.y; a[6] = v1.z; a[7] = v1.w;
    }
    #pragma unroll
    for (int k = 0; k < 8; k++) a[k] *= s;
    int b = __ldg(&off[n]), e = __ldg(&off[n + 1]);
    for (int j = b; j < e; j++) {
        int src = __ldg(&col[j]);
        float t[8];
        if (HIN16) {
            uint4 v = *(const uint4*)((const __half*)hin + (size_t)src * D + lane * 8);
            unpack8(v, t);
        } else {
            const float4* p = (const float4*)((const float*)hin + (size_t)src * D + lane * 8);
            float4 v0 = __ldg(p), v1 = __ldg(p + 1);
            t[0] = v0.x; t[1] = v0.y; t[2] = v0.z; t[3] = v0.w;
            t[4] = v1.x; t[5] = v1.y; t[6] = v1.z; t[7] = v1.w;
        }
        #pragma unroll
        for (int k = 0; k < 8; k++) a[k] += t[k];
    }
    uint4 o = make_uint4(pack_h2(a[0], a[1]), pack_h2(a[2], a[3]),
                         pack_h2(a[4], a[5]), pack_h2(a[6], a[7]));
    *(uint4*)(aggh + (size_t)n * D + lane * 8) = o;
}

__global__ void pool_scatter(float* __restrict__ pool, float* __restrict__ cnt,
                             const __half* __restrict__ h, const void* __restrict__ batch) {
    int wid = (int)(((size_t)blockIdx.x * blockDim.x + threadIdx.x) >> 5);
    if (wid >= NN) return;
    int lane = threadIdx.x & 31;
    long long g = load_index(batch, wid, g_is64);
    uint4 v = *(const uint4*)(h + (size_t)wid * D + lane * 8);
    float f[8];
    unpack8(v, f);
    float* pd = pool + (size_t)g * D + lane * 8;
    red_add_v4(pd,     make_float4(f[0], f[1], f[2], f[3]));
    red_add_v4(pd + 4, make_float4(f[4], f[5], f[6], f[7]));
    if (lane == 0) atomicAdd(&cnt[g], 1.0f);
}

__global__ void zero_pool(float* __restrict__ pool, float* __restrict__ cnt) {
    int i = blockIdx.x * blockDim.x + threadIdx.x;
    if (i < NG * D / 4) ((float4*)pool)[i] = make_float4(0.f, 0.f, 0.f, 0.f);
    if (i < NG) cnt[i] = 0.f;
}

__global__ void normalize_pool(float* __restrict__ pool, const float* __restrict__ cnt) {
    int i = blockIdx.x * blockDim.x + threadIdx.x;
    if (i < NG * D / 4) {
        int g = i >> 6;
        float s = 1.0f / fmaxf(__ldg(&cnt[g]), 1.0f);
        float4 v = ((float4*)pool)[i];
        v.x *= s; v.y *= s; v.z *= s; v.w *= s;
        ((float4*)pool)[i] = v;
    }
}

// ---------------- FUSED GIN layer: h = BN(relu( relu(aggh@W1+b1) @ W2 + b2 )) ----------------
// 64-row tiles; t [64,512] lives in SMEM in phase-2 A-fragment layout. 2 CTAs/SM.
// SMEM (u32): sT 16384 | sA 2x512 | sB 2x2048.  Total 84 KB dynamic.
constexpr int SMEM_FUSED = (16384 + 1024 + 4096) * 4;

__global__ __launch_bounds__(256, 2)
void fused_layer(const __half* __restrict__ aggh,
                 const uint4* __restrict__ Wf1, const float* __restrict__ b1,
                 const uint4* __restrict__ Wf2, const float* __restrict__ b2,
                 __half* __restrict__ hout,
                 const float* __restrict__ bns, const float* __restrict__ bnb)
{
    extern __shared__ uint32_t sm[];
    uint32_t* sT = sm;                           // 32 ktiles x 512
    uint32_t* sA = sm + 16384;                   // 2 stages x 512
    uint4*    sB = (uint4*)(sm + 16384 + 1024);  // 2 stages x 512 uint4

    const int tid  = threadIdx.x;
    const int w    = tid >> 5, lane = tid & 31;
    const int wm   = w >> 1,   wn   = w & 1;     // 4(m) x 2(n)
    const int eg   = lane >> 2, tig = lane & 3;
    const int row0 = blockIdx.x * 64;

    // A producer (threads < 128): row rr in [0,64), k-half kk8
    const bool aprod = tid < 128;
    const int rr   = (tid & 127) >> 1;
    const int kk8  = tid & 1;
    const int amt  = rr >> 4;
    const int ag   = rr & 7;
    const int areg = ((rr >> 3) & 1) + 2 * kk8;
    const int soff = amt * 128 + areg * 32 + ag * 4;
    int rrg = row0 + rr; if (rrg > NN - 1) rrg = NN - 1;
    const __half* Arow = aggh + (size_t)rrg * D + kk8 * 8;

    float4 acc[16];
    uint4 avh;

    // ================= PHASE 1: t = relu(aggh @ W1 + b1), two 256-col passes =================
    // B stage layout: [blk(2)][within(256)] uint4; src = Bbase + (blk*16 + kt)*256 + within.
    #pragma unroll 1
    for (int nhalf = 0; nhalf < 2; nhalf++) {
        #pragma unroll
        for (int j = 0; j < 16; j++) acc[j] = make_float4(0.f, 0.f, 0.f, 0.f);
        const uint4* Bbase = Wf1 + (size_t)nhalf * 2 * 16 * 256;  // blocks nhalf*2, nhalf*2+1

        {   // prologue kt=0
            if (aprod) avh = *(const uint4*)Arow;
            int i0 = tid, i1 = tid + 256;
            cp_async16s(smem_u32(&sB[i0]), Bbase + (((i0 >> 8) * 16 + 0) * 256) + (i0 & 255));
            cp_async16s(smem_u32(&sB[i1]), Bbase + (((i1 >> 8) * 16 + 0) * 256) + (i1 & 255));
            cp_commit();
            if (aprod) *(uint4*)(&sA[soff]) = avh;
            cp_wait<0>();
            __syncthreads();
        }

        for (int kt = 0; kt < 16; kt++) {
            const int st = kt & 1;
            const bool hn = (kt + 1) < 16;
            if (hn) {
                if (aprod) avh = *(const uint4*)(Arow + (kt + 1) * 16);
                int i0 = tid, i1 = tid + 256;
                cp_async16s(smem_u32(&sB[(st ^ 1) * 512 + i0]),
                            Bbase + (((i0 >> 8) * 16 + kt + 1) * 256) + (i0 & 255));
                cp_async16s(smem_u32(&sB[(st ^ 1) * 512 + i1]),
                            Bbase + (((i1 >> 8) * 16 + kt + 1) * 256) + (i1 & 255));
                cp_commit();
            }
            const uint32_t* ab = sA + st * 512 + wm * 128 + lane;
            uint32_t a0 = ab[0], a1 = ab[32], a2 = ab[64], a3 = ab[96];
            const uint4* bb = sB + st * 512 + wn * 256;
            #pragma unroll
            for (int jp = 0; jp < 8; jp++) {
                uint4 b = bb[jp * 32 + lane];
                mma_f16(acc[jp * 2],     a0, a1, a2, a3, b.x, b.y);
                mma_f16(acc[jp * 2 + 1], a0, a1, a2, a3, b.z, b.w);
            }
            if (hn) {
                if (aprod) *(uint4*)(&sA[(st ^ 1) * 512 + soff]) = avh;
                cp_wait<0>();
            }
            __syncthreads();
        }

        // bias + relu + pack into sT (phase-2 A-fragment layout)
        #pragma unroll
        for (int j = 0; j < 16; j++) {
            const int cb = nhalf * 256 + wn * 128 + j * 8 + tig * 2;
            const float2 bi = *(const float2*)(b1 + cb);
            float4 v = acc[j];
            float lx = fmaxf(v.x + bi.x, 0.f), ly = fmaxf(v.y + bi.y, 0.f);
            float hx = fmaxf(v.z + bi.x, 0.f), hy = fmaxf(v.w + bi.y, 0.f);
            const int ktile = nhalf * 16 + wn * 8 + (j >> 1);
            const int base  = ktile * 512 + wm * 128 + (j & 1) * 64 + lane;
            sT[base]      = pack_h2(lx, ly);
            sT[base + 32] = pack_h2(hx, hy);
        }
        __syncthreads();
    }

    // ================= PHASE 2: h = BN(relu(t @ W2 + b2)), K=512 (32 ktiles) =================
    #pragma unroll
    for (int j = 0; j < 16; j++) acc[j] = make_float4(0.f, 0.f, 0.f, 0.f);

    {   // prologue kt=0
        int i0 = tid, i1 = tid + 256;
        cp_async16s(smem_u32(&sB[i0]), Wf2 + (((i0 >> 8) * 32 + 0) * 256) + (i0 & 255));
        cp_async16s(smem_u32(&sB[i1]), Wf2 + (((i1 >> 8) * 32 + 0) * 256) + (i1 & 255));
        cp_commit();
        cp_wait<0>();
        __syncthreads();
    }

    for (int kt = 0; kt < 32; kt++) {
        const int st = kt & 1;
        const bool hn = (kt + 1) < 32;
        if (hn) {
            int i0 = tid, i1 = tid + 256;
            cp_async16s(smem_u32(&sB[(st ^ 1) * 512 + i0]),
                        Wf2 + (((i0 >> 8) * 32 + kt + 1) * 256) + (i0 & 255));
            cp_async16s(smem_u32(&sB[(st ^ 1) * 512 + i1]),
                        Wf2 + (((i1 >> 8) * 32 + kt + 1) * 256) + (i1 & 255));
            cp_commit();
        }
        const uint32_t* ab = sT + kt * 512 + wm * 128 + lane;
        uint32_t a0 = ab[0], a1 = ab[32], a2 = ab[64], a3 = ab[96];
        const uint4* bb = sB + st * 512 + wn * 256;
        #pragma unroll
        for (int jp = 0; jp < 8; jp++) {
            uint4 b = bb[jp * 32 + lane];
            mma_f16(acc[jp * 2],     a0, a1, a2, a3, b.x, b.y);
            mma_f16(acc[jp * 2 + 1], a0, a1, a2, a3, b.z, b.w);
        }
        if (hn) cp_wait<0>();
        __syncthreads();
    }

    // epilogue: BN(relu(acc + b2)) -> hout fp16
    #pragma unroll
    for (int j = 0; j < 16; j++) {
        const int cb = wn * 128 + j * 8 + tig * 2;
        const float2 bi = *(const float2*)(b2 + cb);
        const float2 bs = *(const float2*)(bns + cb);
        const float2 bt = *(const float2*)(bnb + cb);
        float4 v = acc[j];
        const int r0 = row0 + wm * 16 + eg;
        float lx = fmaxf(v.x + bi.x, 0.f), ly = fmaxf(v.y + bi.y, 0.f);
        float hx = fmaxf(v.z + bi.x, 0.f), hy = fmaxf(v.w + bi.y, 0.f);
        lx = fmaf(lx, bs.x, bt.x); ly = fmaf(ly, bs.y, bt.y);
        hx = fmaf(hx, bs.x, bt.x); hy = fmaf(hy, bs.y, bt.y);
        if (r0 < NN)     *(__half2*)(hout + (size_t)r0 * D + cb)       = __floats2half2_rn(lx, ly);
        if (r0 + 8 < NN) *(__half2*)(hout + (size_t)(r0 + 8) * D + cb) = __floats2half2_rn(hx, hy);
    }
}

// ---------------- fp16 mma.sync GEMM (head only), 128x128 CTA, 2 CTAs/SM ----------------
template<int EPI, bool AH, bool CH>
__global__ __launch_bounds__(256, 2)
void hgemm(const void* __restrict__ Ain, const uint4* __restrict__ Wf,
           const float* __restrict__ bias, void* __restrict__ Cout,
           int M, int K, int Ntotal,
           const float* __restrict__ bns, const float* __restrict__ bnb)
{
    __shared__ uint32_t smu[2][2048];
    const int tid  = threadIdx.x;
    const int w    = tid >> 5, lane = tid & 31;
    const int wm   = w >> 1,   wn   = w & 1;
    const int row0 = blockIdx.y * 128;
    const int col0 = blockIdx.x * 128;
    const int K16  = K >> 4;
    const int rr   = tid >> 1;
    const int kk8  = tid & 1;
    const int mt   = rr >> 4;
    const int g    = rr & 7;
    const int reg  = ((rr >> 3) & 1) + 2 * kk8;
    const int soff = mt * 128 + reg * 32 + g * 4;
    int rrg = row0 + rr; if (rrg > M - 1) rrg = M - 1;
    const __half* Ah = (const __half*)Ain;
    const float*  Af = (const float*)Ain;
    const uint4*  Bsrc = Wf + (size_t)blockIdx.x * K16 * 256;

    float4 acc[2][8];
    #pragma unroll
    for (int i = 0; i < 2; i++)
        #pragma unroll
        for (int j = 0; j < 8; j++) acc[i][j] = make_float4(0.f, 0.f, 0.f, 0.f);
    uint4  avh;
    float4 av0, av1;
    {
        if (AH) avh = *(const uint4*)(Ah + (size_t)rrg * K + kk8 * 8);
        else { const float4* p = (const float4*)(Af + (size_t)rrg * K + kk8 * 8);
               av0 = __ldg(p); av1 = __ldg(p + 1); }
        cp_async16s(smem_u32(&smu[0][1024 + tid * 4]), Bsrc + tid);
        cp_commit();
        uint4 st;
        if (AH) st = avh;
        else st = make_uint4(pack_h2(av0.x, av0.y), pack_h2(av0.z, av0.w),
                             pack_h2(av1.x, av1.y), pack_h2(av1.z, av1.w));
        *(uint4*)(&smu[0][soff]) = st;
        cp_wait<0>();
        __syncthreads();
    }
    for (int kt = 0; kt < K16; kt++) {
        const int st = kt & 1;
        const bool hn = (kt + 1) < K16;
        if (hn) {
            if (AH) avh = *(const uint4*)(Ah + (size_t)rrg * K + (kt + 1) * 16 + kk8 * 8);
            else { const float4* p = (const float4*)(Af + (size_t)rrg * K + (kt + 1) * 16 + kk8 * 8);
                   av0 = __ldg(p); av1 = __ldg(p + 1); }
            cp_async16s(smem_u32(&smu[st ^ 1][1024 + tid * 4]), Bsrc + (size_t)(kt + 1) * 256 + tid);
            cp_commit();
        }
        const uint32_t* sA = smu[st];
        const uint32_t* sB = smu[st] + 1024;
        uint4 b[4];
        #pragma unroll
        for (int jp = 0; jp < 4; jp++)
            b[jp] = *(const uint4*)(sB + ((wn * 4 + jp) * 32 + lane) * 4);
        #pragma unroll
        for (int i = 0; i < 2; i++) {
            const uint32_t* ab = sA + (wm * 2 + i) * 128 + lane;
            uint32_t a0 = ab[0], a1 = ab[32], a2 = ab[64], a3 = ab[96];
            #pragma unroll
            for (int jp = 0; jp < 4; jp++) {
                mma_f16(acc[i][jp * 2],     a0, a1, a2, a3, b[jp].x, b[jp].y);
                mma_f16(acc[i][jp * 2 + 1], a0, a1, a2, a3, b[jp].z, b[jp].w);
            }
        }
        if (hn) {
            uint4 stv;
            if (AH) stv = avh;
            else stv = make_uint4(pack_h2(av0.x, av0.y), pack_h2(av0.z, av0.w),
                                  pack_h2(av1.x, av1.y), pack_h2(av1.z, av1.w));
            *(uint4*)(&smu[st ^ 1][soff]) = stv;
            cp_wait<0>();
        }
        __syncthreads();
    }
    const int eg = lane >> 2, tig = lane & 3;
    float*  Cf = (float*)Cout;
    __half* Ch = (__half*)Cout;
    #pragma unroll
    for (int j = 0; j < 8; j++) {
        const int cb = col0 + wn * 64 + j * 8 + tig * 2;
        const float2 bi = *(const float2*)(bias + cb);
        float2 bs = make_float2(0.f, 0.f), bt = make_float2(0.f, 0.f);
        if (EPI == 2) { bs = *(const float2*)(bns + cb); bt = *(const float2*)(bnb + cb); }
        #pragma unroll
        for (int i = 0; i < 2; i++) {
            const int r0 = row0 + wm * 32 + i * 16 + eg;
            float4 v = acc[i][j];
            float2 lo = make_float2(v.x + bi.x, v.y + bi.y);
            float2 hi = make_float2(v.z + bi.x, v.w + bi.y);
            if (EPI >= 1) {
                lo.x = fmaxf(lo.x, 0.f); lo.y = fmaxf(lo.y, 0.f);
                hi.x = fmaxf(hi.x, 0.f); hi.y = fmaxf(hi.y, 0.f);
            }
            if (EPI == 2) {
                lo.x = fmaf(lo.x, bs.x, bt.x); lo.y = fmaf(lo.y, bs.y, bt.y);
                hi.x = fmaf(hi.x, bs.x, bt.x); hi.y = fmaf(hi.y, bs.y, bt.y);
            }
            if (r0 < M) {
                if (CH) *(__half2*)(Ch + (size_t)r0 * Ntotal + cb) = __floats2half2_rn(lo.x, lo.y);
                else    *(float2*)(Cf + (size_t)r0 * Ntotal + cb) = lo;
            }
            if (r0 + 8 < M) {
                if (CH) *(__half2*)(Ch + (size_t)(r0 + 8) * Ntotal + cb) = __floats2half2_rn(hi.x, hi.y);
                else    *(float2*)(Cf + (size_t)(r0 + 8) * Ntotal + cb) = hi;
            }
        }
    }
}

// ---------------- launcher ----------------
extern "C" void kernel_launch(void* const* d_in, const int* in_sizes, int n_in,
                              void* d_out, int out_size)
{
    const float* x     = (const float*)d_in[0];
    const void*  ei    = d_in[1];
    const void*  batch = d_in[2];
    const float* w1    = (const float*)d_in[3];
    const float* b1    = (const float*)d_in[4];
    const float* w2    = (const float*)d_in[5];
    const float* b2    = (const float*)d_in[6];
    const float* eps   = (const float*)d_in[7];
    const float* bng   = (const float*)d_in[8];
    const float* bnbt  = (const float*)d_in[9];
    const float* bnm   = (const float*)d_in[10];
    const float* bnv   = (const float*)d_in[11];
    const float* wp1   = (const float*)d_in[12];
    const float* bp1   = (const float*)d_in[13];
    const float* wp2   = (const float*)d_in[14];
    const float* bp2   = (const float*)d_in[15];
    float* out = (float*)d_out;

    float *pool, *cnt, *p1, *bns, *bnb;
    __half *aggh, *h;
    int *deg, *off, *col, *bsum;
    uint4 *wf1, *wf2, *wfp1, *wfp2;
    cudaGetSymbolAddress((void**)&aggh, g_aggh);
    cudaGetSymbolAddress((void**)&h,    g_h);
    cudaGetSymbolAddress((void**)&pool, g_pool);
    cudaGetSymbolAddress((void**)&cnt,  g_cnt);
    cudaGetSymbolAddress((void**)&p1,   g_p1);
    cudaGetSymbolAddress((void**)&bns,  g_bns);
    cudaGetSymbolAddress((void**)&bnb,  g_bnb);
    cudaGetSymbolAddress((void**)&deg,  g_deg);
    cudaGetSymbolAddress((void**)&off,  g_off);
    cudaGetSymbolAddress((void**)&col,  g_col);
    cudaGetSymbolAddress((void**)&bsum, g_bsum);
    cudaGetSymbolAddress((void**)&wf1,  g_wf1);
    cudaGetSymbolAddress((void**)&wf2,  g_wf2);
    cudaGetSymbolAddress((void**)&wfp1, g_wfp1);
    cudaGetSymbolAddress((void**)&wfp2, g_wfp2);

    cudaFuncSetAttribute(fused_layer, cudaFuncAttributeMaxDynamicSharedMemorySize, SMEM_FUSED);

    detect_idx<<<1, 1>>>((const unsigned int*)ei);
    bn_precompute<<<(5 * D + 255) / 256, 256>>>(bng, bnbt, bnm, bnv);
    for (int l = 0; l < LGIN; l++) {
        prep_wh<<<(D * HID2 / 8 + 255) / 256, 256>>>(w1 + (size_t)l * D * HID2,
                                                     wf1 + (size_t)l * D * HID2 / 8, D, HID2);
        prep_wh<<<(HID2 * D / 8 + 255) / 256, 256>>>(w2 + (size_t)l * HID2 * D,
                                                     wf2 + (size_t)l * HID2 * D / 8, HID2, D);
    }
    prep_wh<<<(D * NHID / 8 + 255) / 256, 256>>>(wp1, wfp1, D, NHID);
    prep_wh<<<(NHID * NOUT / 8 + 255) / 256, 256>>>(wp2, wfp2, NHID, NOUT);

    // ---- CSR build ----
    const int nnb = (NN + 255) / 256, neb = (NE + 255) / 256;
    csr_zero<<<nnb, 256>>>(deg);
    csr_hist<<<neb, 256>>>(ei, deg);
    csr_scan1<<<SCAN_BLKS, 1024>>>(deg, off, bsum);
    csr_scan2<<<1, 128>>>(bsum);
    csr_scan3<<<nnb, 256>>>(off, bsum);
    csr_zero<<<nnb, 256>>>(deg);
    csr_fill<<<neb, 256>>>(ei, off, deg, col);

    const int bnidx[4] = {0, 0, 1, 2};           // reference's bn-index bug, kept
    const int node_blocks   = (int)(((size_t)NN * 32 + 255) / 256);
    const int poolv4_blocks = (NG * D / 4 + 255) / 256;
    const int ftiles = (NN + 63) / 64;           // 1563

    for (int l = 0; l < LGIN; l++) {
        if (l == 0) aggregate<false><<<node_blocks, 256>>>(aggh, x, off, col, eps, l);
        else        aggregate<true ><<<node_blocks, 256>>>(aggh, h, off, col, eps, l);
        fused_layer<<<ftiles, 256, SMEM_FUSED>>>(
            aggh,
            wf1 + (size_t)l * D * HID2 / 8, b1 + (size_t)l * HID2,
            wf2 + (size_t)l * HID2 * D / 8, b2 + (size_t)l * D,
            h, bns + bnidx[l] * D, bnb + bnidx[l] * D);
    }

    zero_pool<<<poolv4_blocks, 256>>>(pool, cnt);
    pool_scatter<<<node_blocks, 256>>>(pool, cnt, h, batch);
    normalize_pool<<<poolv4_blocks, 256>>>(pool, cnt);

    hgemm<1, false, false><<<dim3(NHID / 128, NG / 128), 256>>>(
        pool, wfp1, bp1, p1, NG, D, NHID, nullptr, nullptr);
    hgemm<0, false, false><<<dim3(NOUT / 128, NG / 128), 256>>>(
        p1, wfp2, bp2, out, NG, NHID, NOUT, nullptr, nullptr);
}